// round 8
// baseline (speedup 1.0000x reference)
#include <cuda_runtime.h>
#include <cuda_fp16.h>
#include <mma.h>
#include <math.h>
#include <stdint.h>

using namespace nvcuda;

#define NN 4096
#define ND 256
#define HID 64
#define NH 4
#define NC 16

// ---------------- scratch (static device globals) ---------------------------
__device__ float  g_H1[NN*ND];
__device__ float  g_F1[NH*NN];
__device__ float  g_F2[NH*NN];
__device__ unsigned g_f2max1u[NH];
__device__ float4 g_bdf1[NH*NN];
__device__ uint8_t g_adj8[(size_t)NN*NN];
__device__ __half g_Vb[(size_t)NH*2*NN*80];  // [head][hi|lo][j][80] (col64 = ones)
__device__ float  g_H2[NN*ND];
__device__ float  g_G2[NN*NC];
__device__ __half g_G2b[2*NN*32];            // [hi|lo][j][32] (col16 = ones)
__device__ float  g_f1b[NN];
__device__ float  g_f2b[NN];
__device__ unsigned g_f2max2u[1];
__device__ float4 g_bdf2[NN];

// ---------------- ordered-float encoding for atomicMax -----------------------
__device__ __forceinline__ unsigned fenc(float f){
    unsigned u = __float_as_uint(f);
    return (u & 0x80000000u) ? ~u : (u | 0x80000000u);
}
__device__ __forceinline__ float fdec(unsigned u){
    return (u & 0x80000000u) ? __uint_as_float(u ^ 0x80000000u) : __uint_as_float(~u);
}
__device__ __forceinline__ uint32_t packh(__half a, __half b){
    return (uint32_t)__half_as_ushort(a) | ((uint32_t)__half_as_ushort(b) << 16);
}

// ---------------- K0: init atomic-max cells -----------------------------------
__global__ void init_kernel(){
    int t = threadIdx.x;
    if (t < NH) g_f2max1u[t] = 0u;
    if (t == NH) g_f2max2u[0] = 0u;
}

// ---------------- K1: adjacency -> bytes --------------------------------------
__global__ void adj8_kernel(const int* __restrict__ adj){
    size_t idx = (size_t)blockIdx.x*256 + threadIdx.x;   // grid 4096
    const int4* s = reinterpret_cast<const int4*>(adj) + idx*4;
    uint32_t w[4];
#pragma unroll
    for (int q = 0; q < 4; q++){
        int4 v = s[q];
        w[q] = (v.x != 0 ? 1u : 0u) | (v.y != 0 ? 1u : 0u) << 8
             | (v.z != 0 ? 1u : 0u) << 16 | (v.w != 0 ? 1u : 0u) << 24;
    }
    reinterpret_cast<uint4*>(g_adj8)[idx] = make_uint4(w[0], w[1], w[2], w[3]);
}

// ---------------- K2: H1 = x @ W1_flat^T --------------------------------------
__global__ void gemm1_kernel(const float* __restrict__ X, const float* __restrict__ W){
    __shared__ float sx[64][17];
    __shared__ float sw[64][17];
    int tid = threadIdx.x;
    int tx = tid & 15, ty = tid >> 4;
    int mb = blockIdx.x * 64, nb = blockIdx.y * 64;
    float acc[4][4] = {};
    for (int kb = 0; kb < ND; kb += 16){
        for (int u = tid; u < 64*16; u += 256){
            int m = u >> 4, k = u & 15;
            sx[m][k] = X[(mb + m)*ND + kb + k];
        }
        for (int u = tid; u < 64*16; u += 256){
            int n = u >> 4, k = u & 15;
            sw[n][k] = W[(nb + n)*ND + kb + k];
        }
        __syncthreads();
#pragma unroll
        for (int k = 0; k < 16; k++){
            float a[4], b[4];
#pragma unroll
            for (int r = 0; r < 4; r++){ a[r] = sx[ty*4 + r][k]; b[r] = sw[tx*4 + r][k]; }
#pragma unroll
            for (int i = 0; i < 4; i++)
#pragma unroll
                for (int j = 0; j < 4; j++) acc[i][j] += a[i]*b[j];
        }
        __syncthreads();
    }
#pragma unroll
    for (int i = 0; i < 4; i++)
#pragma unroll
        for (int j = 0; j < 4; j++)
            g_H1[(mb + ty*4 + i)*ND + nb + tx*4 + j] = acc[i][j];
}

// ---------------- K3: f1/f2 per head + fused max(f2) --------------------------
__global__ void fvec1_kernel(const float* __restrict__ a1, const float* __restrict__ a2){
    __shared__ float s1[NH][HID], s2[NH][HID];
    __shared__ float smax[8];
    int tid = threadIdx.x;
    s1[tid >> 6][tid & 63] = a1[tid];
    s2[tid >> 6][tid & 63] = a2[tid];
    __syncthreads();
    int idx = blockIdx.x*256 + tid;   // grid 64; one head per block
    int h = idx >> 12, i = idx & (NN-1);
    const float* hr = g_H1 + i*ND + h*HID;
    float f1 = 0.f, f2 = 0.f;
#pragma unroll 8
    for (int d = 0; d < HID; d++){
        float v = hr[d];
        f1 += v * s1[h][d];
        f2 += v * s2[h][d];
    }
    g_F1[idx] = f1; g_F2[idx] = f2;
    // block max of f2 -> one atomic
    float m = f2;
#pragma unroll
    for (int off = 16; off > 0; off >>= 1) m = fmaxf(m, __shfl_down_sync(0xffffffffu, m, off));
    if ((tid & 31) == 0) smax[tid >> 5] = m;
    __syncthreads();
    if (tid == 0){
        float mm = smax[0];
#pragma unroll
        for (int k = 1; k < 8; k++) mm = fmaxf(mm, smax[k]);
        atomicMax(&g_f2max1u[h], fenc(mm));
    }
}

// ---------------- K4: (f2, B, D) table per head -------------------------------
__global__ void bdf1_kernel(){
    int idx = blockIdx.x*256 + threadIdx.x;
    int h = idx >> 12;
    float f2 = g_F2[idx];
    float d  = f2 - fdec(g_f2max1u[h]);
    g_bdf1[idx] = make_float4(f2, expf(d), expf(0.01f*d), 0.f);
}

// ---------------- K5: V fp16 hi/lo with ones column ---------------------------
__global__ void vbf_kernel(){
    int tid = threadIdx.x;            // grid (64, NH), 256 threads
    int j = blockIdx.x*64 + (tid >> 2);
    int h = blockIdx.y;
    int fg = tid & 3;
    const float4* src = reinterpret_cast<const float4*>(g_H1 + (size_t)j*ND + h*HID + fg*16);
    __half* dhi = g_Vb + (((size_t)(h*2 + 0))*NN + j)*80 + fg*16;
    __half* dlo = g_Vb + (((size_t)(h*2 + 1))*NN + j)*80 + fg*16;
    uint32_t ph[8], pl[8];
#pragma unroll
    for (int q = 0; q < 4; q++){
        float4 v = src[q];
        float e[4] = {v.x, v.y, v.z, v.w};
        __half hh[4], ll[4];
#pragma unroll
        for (int k = 0; k < 4; k++){
            hh[k] = __float2half_rn(e[k]);
            ll[k] = __float2half_rn(e[k] - __half2float(hh[k]));
        }
        ph[q*2]   = packh(hh[0], hh[1]); ph[q*2+1] = packh(hh[2], hh[3]);
        pl[q*2]   = packh(ll[0], ll[1]); pl[q*2+1] = packh(ll[2], ll[3]);
    }
    uint4* oh = reinterpret_cast<uint4*>(dhi);
    uint4* ol = reinterpret_cast<uint4*>(dlo);
    oh[0] = make_uint4(ph[0],ph[1],ph[2],ph[3]);
    oh[1] = make_uint4(ph[4],ph[5],ph[6],ph[7]);
    ol[0] = make_uint4(pl[0],pl[1],pl[2],pl[3]);
    ol[1] = make_uint4(pl[4],pl[5],pl[6],pl[7]);
    if (fg == 3){
        uint4* zh = reinterpret_cast<uint4*>(dhi + 16);
        uint4* zl = reinterpret_cast<uint4*>(dlo + 16);
        zh[0] = make_uint4(0x00003C00u, 0u, 0u, 0u);
        zh[1] = make_uint4(0u, 0u, 0u, 0u);
        zl[0] = make_uint4(0u, 0u, 0u, 0u);
        zl[1] = make_uint4(0u, 0u, 0u, 0u);
    }
}

// ---------------- K6: attn1 wmma fp16, 8 warps (4 rowslices x 2 ntslices) -----
__global__ void __launch_bounds__(256) attn1_wmma_kernel(){
    __shared__ __align__(16) unsigned char smem[36864];
    __half* sAh = (__half*)(smem);             // [64][64] 8KB
    __half* sAl = (__half*)(smem + 8192);      // 8KB
    __half* sBh = (__half*)(smem + 16384);     // [64][80] 10KB
    __half* sBl = (__half*)(smem + 26624);     // 10KB
    float*  sepi = (float*)smem;               // epilogue [64][80] 20KB (reuse)
    __shared__ float sf2[64], sBv[64], sDv[64];

    int tid = threadIdx.x;
    int wid = tid >> 5;
    int wr = wid & 3, wc = wid >> 2;
    int row0 = blockIdx.x * 64;
    int h = blockIdx.y;
    int r = tid >> 2, jg = tid & 3;           // phase-A: row, 16-j group

    float f1 = g_F1[h*NN + row0 + r];
    float tt = f1 + fdec(g_f2max1u[h]);
    float M  = tt > 0.f ? tt : 0.01f*tt;
    float alpha = expf(tt - M), beta = expf(0.01f*tt - M);

    // wc==0 -> nt {0,1,2}; wc==1 -> nt {3,4}
    wmma::fragment<wmma::accumulator,16,16,16,float> G[3];
    int ntn = wc == 0 ? 3 : 2;
    int ntb = wc == 0 ? 0 : 3;
#pragma unroll
    for (int q = 0; q < 3; q++) wmma::fill_fragment(G[q], 0.f);

    const __half* Vh = g_Vb + ((size_t)(h*2 + 0))*NN*80;
    const __half* Vl = g_Vb + ((size_t)(h*2 + 1))*NN*80;
    const uint8_t* adjrow = g_adj8 + (size_t)(row0 + r)*NN;

    for (int t = 0; t < 64; t++){
        int j0 = t * 64;
        __syncthreads();
        if (tid < 64){
            float4 b = g_bdf1[h*NN + j0 + tid];
            sf2[tid] = b.x; sBv[tid] = b.y; sDv[tid] = b.z;
        }
        {   // stage B tile with all 256 threads: part(hi/lo), 40-half chunk, row
            int part = tid & 1, ch = ((tid >> 1) & 1)*40, j = tid >> 2;
            const __half* gsrc = (part ? Vl : Vh) + (size_t)(j0 + j)*80 + ch;
            __half* gdst = (part ? sBl : sBh) + j*80 + ch;
            const uint4* s4 = reinterpret_cast<const uint4*>(gsrc);
            uint4* d4 = reinterpret_cast<uint4*>(gdst);
#pragma unroll
            for (int q = 0; q < 5; q++) d4[q] = s4[q];
        }
        __syncthreads();
        // ---- phase A: 16 weights per thread ----
        uint4 av = *reinterpret_cast<const uint4*>(adjrow + j0 + jg*16);
        uint32_t aw[4] = {av.x, av.y, av.z, av.w};
        uint32_t oh[8], ol[8];
#pragma unroll
        for (int p = 0; p < 8; p++){
            uint32_t hw[2], lw[2];
#pragma unroll
            for (int e = 0; e < 2; e++){
                int jl = 2*p + e;
                int jj = jg*16 + jl;
                uint32_t byte = (aw[jl >> 2] >> ((jl & 3)*8)) & 0xFFu;
                float s = f1 + sf2[jj];
                float w = s > 0.f ? alpha*sBv[jj] : beta*sDv[jj];
                if ((byte == 0u) | (s == 0.f)) w = 0.f;
                __half whf = __float2half_rn(w);
                __half wlf = __float2half_rn(w - __half2float(whf));
                hw[e] = __half_as_ushort(whf);
                lw[e] = __half_as_ushort(wlf);
            }
            oh[p] = hw[0] | (hw[1] << 16);
            ol[p] = lw[0] | (lw[1] << 16);
        }
        {
            uint4* dh = reinterpret_cast<uint4*>(sAh + r*64 + jg*16);
            uint4* dl = reinterpret_cast<uint4*>(sAl + r*64 + jg*16);
            dh[0] = make_uint4(oh[0], oh[1], oh[2], oh[3]);
            dh[1] = make_uint4(oh[4], oh[5], oh[6], oh[7]);
            dl[0] = make_uint4(ol[0], ol[1], ol[2], ol[3]);
            dl[1] = make_uint4(ol[4], ol[5], ol[6], ol[7]);
        }
        __syncthreads();
        // ---- phase B: warp (wr, wc) ----
#pragma unroll
        for (int ks = 0; ks < 4; ks++){
            wmma::fragment<wmma::matrix_a,16,16,16,__half,wmma::row_major> ah, al;
            wmma::load_matrix_sync(ah, sAh + wr*16*64 + ks*16, 64);
            wmma::load_matrix_sync(al, sAl + wr*16*64 + ks*16, 64);
#pragma unroll
            for (int q = 0; q < 3; q++){
                if (q >= ntn) break;
                int nt = ntb + q;
                wmma::fragment<wmma::matrix_b,16,16,16,__half,wmma::row_major> bh, bl;
                wmma::load_matrix_sync(bh, sBh + ks*16*80 + nt*16, 80);
                wmma::load_matrix_sync(bl, sBl + ks*16*80 + nt*16, 80);
                wmma::mma_sync(G[q], ah, bh, G[q]);
                wmma::mma_sync(G[q], al, bh, G[q]);
                wmma::mma_sync(G[q], ah, bl, G[q]);
            }
        }
    }
    // ---- epilogue ----
    __syncthreads();
#pragma unroll
    for (int q = 0; q < 3; q++){
        if (q >= ntn) break;
        wmma::store_matrix_sync(sepi + wr*16*80 + (ntb + q)*16, G[q], 80, wmma::mem_row_major);
    }
    __syncthreads();
    float rz = 1.f / sepi[r*80 + 64];
    float* dst = g_H2 + (size_t)(row0 + r)*ND + h*HID + jg*16;
#pragma unroll
    for (int c = 0; c < 16; c += 4){
        float o[4];
#pragma unroll
        for (int e = 0; e < 4; e++){
            float v = sepi[r*80 + jg*16 + c + e] * rz;
            o[e] = v > 0.f ? v : expm1f(v);
        }
        *reinterpret_cast<float4*>(dst + c) = make_float4(o[0], o[1], o[2], o[3]);
    }
}

// ---------------- K7: G2 = H2 @ W2^T + f-vectors + fused max ------------------
__global__ void gemm2_kernel(const float* __restrict__ W2,
                             const float* __restrict__ a1, const float* __restrict__ a2){
    __shared__ float sW[16][257];
    __shared__ float sa1[16], sa2[16];
    __shared__ float s_u2[16];
    int tid = threadIdx.x;
    for (int u = tid; u < 16*256; u += 256) sW[u >> 8][u & 255] = W2[u];
    if (tid < 16){ sa1[tid] = a1[tid]; sa2[tid] = a2[tid]; }
    __syncthreads();
    int idx = blockIdx.x*256 + tid;
    int i = idx >> 4, c = idx & 15;
    const float4* hr = reinterpret_cast<const float4*>(g_H2 + i*ND);
    float acc = 0.f;
#pragma unroll 4
    for (int k4 = 0; k4 < 64; k4++){
        float4 v = hr[k4];
        acc += v.x*sW[c][k4*4] + v.y*sW[c][k4*4+1] + v.z*sW[c][k4*4+2] + v.w*sW[c][k4*4+3];
    }
    g_G2[idx] = acc;
    float u1 = acc*sa1[c], u2 = acc*sa2[c];
#pragma unroll
    for (int off = 8; off > 0; off >>= 1){
        u1 += __shfl_down_sync(0xffffffffu, u1, off, 16);
        u2 += __shfl_down_sync(0xffffffffu, u2, off, 16);
    }
    if (c == 0){ g_f1b[i] = u1; g_f2b[i] = u2; s_u2[tid >> 4] = u2; }
    __syncthreads();
    if (tid == 0){
        float m = s_u2[0];
#pragma unroll
        for (int k = 1; k < 16; k++) m = fmaxf(m, s_u2[k]);
        atomicMax(g_f2max2u, fenc(m));
    }
}

// ---------------- K8: bdf2 + G2 fp16 hi/lo split ------------------------------
__global__ void bdf2g2_kernel(){
    int row = blockIdx.x*256 + threadIdx.x;   // grid 16
    float f2 = g_f2b[row];
    float d  = f2 - fdec(g_f2max2u[0]);
    g_bdf2[row] = make_float4(f2, expf(d), expf(0.01f*d), 0.f);

    const float4* src = reinterpret_cast<const float4*>(g_G2 + row*NC);
    uint32_t ph[16], pl[16];
#pragma unroll
    for (int q = 0; q < 4; q++){
        float4 v = src[q];
        float e[4] = {v.x, v.y, v.z, v.w};
        __half hh[4], ll[4];
#pragma unroll
        for (int k = 0; k < 4; k++){
            hh[k] = __float2half_rn(e[k]);
            ll[k] = __float2half_rn(e[k] - __half2float(hh[k]));
        }
        ph[q*2]   = packh(hh[0], hh[1]); ph[q*2+1] = packh(hh[2], hh[3]);
        pl[q*2]   = packh(ll[0], ll[1]); pl[q*2+1] = packh(ll[2], ll[3]);
    }
    ph[8] = 0x00003C00u; pl[8] = 0u;
#pragma unroll
    for (int k = 9; k < 16; k++){ ph[k] = 0u; pl[k] = 0u; }
    uint4* dh = reinterpret_cast<uint4*>(g_G2b + ((size_t)0*NN + row)*32);
    uint4* dl = reinterpret_cast<uint4*>(g_G2b + ((size_t)1*NN + row)*32);
#pragma unroll
    for (int k = 0; k < 4; k++){
        dh[k] = make_uint4(ph[4*k], ph[4*k+1], ph[4*k+2], ph[4*k+3]);
        dl[k] = make_uint4(pl[4*k], pl[4*k+1], pl[4*k+2], pl[4*k+3]);
    }
}

// ---------------- K9: attn2 wmma, 8 warps (4 rowslices x 2 nt) ----------------
__global__ void __launch_bounds__(256) attn2_wmma_kernel(float* __restrict__ out){
    __shared__ __align__(16) unsigned char smem[24576];
    __half* sAh = (__half*)(smem);             // [64][64] 8KB
    __half* sAl = (__half*)(smem + 8192);      // 8KB
    __half* sBh = (__half*)(smem + 16384);     // [64][32] 4KB
    __half* sBl = (__half*)(smem + 20480);     // 4KB
    float*  sepi = (float*)smem;               // [64][32] 8KB (reuse)
    __shared__ float sf2[64], sBv[64], sDv[64];

    int tid = threadIdx.x;
    int wid = tid >> 5;
    int wr = wid & 3, wc = wid >> 2;           // wc = nt
    int row0 = blockIdx.x * 64;
    int r = tid >> 2, jg = tid & 3;

    float f1 = g_f1b[row0 + r];
    float tt = f1 + fdec(g_f2max2u[0]);
    float M  = tt > 0.f ? tt : 0.01f*tt;
    float alpha = expf(tt - M), beta = expf(0.01f*tt - M);

    wmma::fragment<wmma::accumulator,16,16,16,float> G;
    wmma::fill_fragment(G, 0.f);

    const uint8_t* adjrow = g_adj8 + (size_t)(row0 + r)*NN;

    for (int t = 0; t < 64; t++){
        int j0 = t * 64;
        __syncthreads();
        if (tid < 64){
            float4 b = g_bdf2[j0 + tid];
            sf2[tid] = b.x; sBv[tid] = b.y; sDv[tid] = b.z;
        }
        if (tid < 128){
            int part = tid & 1, j = tid >> 1;
            const uint4* src = reinterpret_cast<const uint4*>(
                g_G2b + ((size_t)part*NN + j0 + j)*32);
            uint4* dst = reinterpret_cast<uint4*>((part ? sBl : sBh) + j*32);
#pragma unroll
            for (int q = 0; q < 4; q++) dst[q] = src[q];
        }
        __syncthreads();
        uint4 av = *reinterpret_cast<const uint4*>(adjrow + j0 + jg*16);
        uint32_t aw[4] = {av.x, av.y, av.z, av.w};
        uint32_t oh[8], ol[8];
#pragma unroll
        for (int p = 0; p < 8; p++){
            uint32_t hw[2], lw[2];
#pragma unroll
            for (int e = 0; e < 2; e++){
                int jl = 2*p + e;
                int jj = jg*16 + jl;
                uint32_t byte = (aw[jl >> 2] >> ((jl & 3)*8)) & 0xFFu;
                float s = f1 + sf2[jj];
                float w = s > 0.f ? alpha*sBv[jj] : beta*sDv[jj];
                if ((byte == 0u) | (s == 0.f)) w = 0.f;
                __half whf = __float2half_rn(w);
                __half wlf = __float2half_rn(w - __half2float(whf));
                hw[e] = __half_as_ushort(whf);
                lw[e] = __half_as_ushort(wlf);
            }
            oh[p] = hw[0] | (hw[1] << 16);
            ol[p] = lw[0] | (lw[1] << 16);
        }
        {
            uint4* dh = reinterpret_cast<uint4*>(sAh + r*64 + jg*16);
            uint4* dl = reinterpret_cast<uint4*>(sAl + r*64 + jg*16);
            dh[0] = make_uint4(oh[0], oh[1], oh[2], oh[3]);
            dh[1] = make_uint4(oh[4], oh[5], oh[6], oh[7]);
            dl[0] = make_uint4(ol[0], ol[1], ol[2], ol[3]);
            dl[1] = make_uint4(ol[4], ol[5], ol[6], ol[7]);
        }
        __syncthreads();
#pragma unroll
        for (int ks = 0; ks < 4; ks++){
            wmma::fragment<wmma::matrix_a,16,16,16,__half,wmma::row_major> ah, al;
            wmma::load_matrix_sync(ah, sAh + wr*16*64 + ks*16, 64);
            wmma::load_matrix_sync(al, sAl + wr*16*64 + ks*16, 64);
            wmma::fragment<wmma::matrix_b,16,16,16,__half,wmma::row_major> bh, bl;
            wmma::load_matrix_sync(bh, sBh + ks*16*32 + wc*16, 32);
            wmma::load_matrix_sync(bl, sBl + ks*16*32 + wc*16, 32);
            wmma::mma_sync(G, ah, bh, G);
            wmma::mma_sync(G, al, bh, G);
            wmma::mma_sync(G, ah, bl, G);
        }
    }
    __syncthreads();
    wmma::store_matrix_sync(sepi + wr*16*32 + wc*16, G, 32, wmma::mem_row_major);
    __syncthreads();
    float rz = 1.f / sepi[r*32 + 16];
    float* dst = out + (size_t)(row0 + r)*NC + jg*4;
    float o[4];
#pragma unroll
    for (int e = 0; e < 4; e++) o[e] = sepi[r*32 + jg*4 + e] * rz;
    *reinterpret_cast<float4*>(dst) = make_float4(o[0], o[1], o[2], o[3]);
}

// ---------------- launch ------------------------------------------------------
extern "C" void kernel_launch(void* const* d_in, const int* in_sizes, int n_in,
                              void* d_out, int out_size){
    const float* x    = (const float*)d_in[0];
    const int*   adj  = (const int*)  d_in[1];
    const float* W1   = (const float*)d_in[2];
    const float* a1_1 = (const float*)d_in[3];
    const float* a2_1 = (const float*)d_in[4];
    const float* W2   = (const float*)d_in[5];
    const float* a1_2 = (const float*)d_in[6];
    const float* a2_2 = (const float*)d_in[7];
    float* out = (float*)d_out;

    init_kernel<<<1, 32>>>();
    adj8_kernel<<<4096, 256>>>(adj);
    gemm1_kernel<<<dim3(64, 4), 256>>>(x, W1);
    fvec1_kernel<<<64, 256>>>(a1_1, a2_1);
    bdf1_kernel<<<64, 256>>>();
    vbf_kernel<<<dim3(64, NH), 256>>>();
    attn1_wmma_kernel<<<dim3(64, NH), 256>>>();
    gemm2_kernel<<<256, 256>>>(W2, a1_2, a2_2);
    bdf2g2_kernel<<<16, 256>>>();
    attn2_wmma_kernel<<<64, 256>>>(out);
}

// round 9
// speedup vs baseline: 1.2240x; 1.2240x over previous
#include <cuda_runtime.h>
#include <cuda_fp16.h>
#include <mma.h>
#include <math.h>
#include <stdint.h>

using namespace nvcuda;

#define NN 4096
#define ND 256
#define HID 64
#define NH 4
#define NC 16

// ---------------- scratch (static device globals) ---------------------------
__device__ float  g_H1[NN*ND];
__device__ float  g_F1[NH*NN];
__device__ float  g_F2[NH*NN];
__device__ unsigned g_f2max1u[NH];
__device__ float4 g_bdf1[NH*NN];
__device__ uint8_t g_adj8[(size_t)NN*NN];
__device__ __half g_Vb[(size_t)NH*2*NN*80];  // [head][hi|lo][j][80] (col64 = ones)
__device__ float  g_H2[NN*ND];
__device__ float  g_G2[NN*NC];
__device__ __half g_G2b[2*NN*32];            // [hi|lo][j][32] (col16 = ones)
__device__ float  g_f1b[NN];
__device__ float  g_f2b[NN];
__device__ unsigned g_f2max2u[1];
__device__ float4 g_bdf2[NN];

// ---------------- helpers -----------------------------------------------------
__device__ __forceinline__ unsigned fenc(float f){
    unsigned u = __float_as_uint(f);
    return (u & 0x80000000u) ? ~u : (u | 0x80000000u);
}
__device__ __forceinline__ float fdec(unsigned u){
    return (u & 0x80000000u) ? __uint_as_float(u ^ 0x80000000u) : __uint_as_float(~u);
}
__device__ __forceinline__ uint32_t packh(__half a, __half b){
    return (uint32_t)__half_as_ushort(a) | ((uint32_t)__half_as_ushort(b) << 16);
}

// ---------------- K0: init atomic-max cells -----------------------------------
__global__ void init_kernel(){
    int t = threadIdx.x;
    if (t < NH) g_f2max1u[t] = 0u;
    if (t == NH) g_f2max2u[0] = 0u;
}

// ---------------- K1: adjacency -> bytes --------------------------------------
__global__ void adj8_kernel(const int* __restrict__ adj){
    size_t idx = (size_t)blockIdx.x*256 + threadIdx.x;   // grid 4096
    const int4* s = reinterpret_cast<const int4*>(adj) + idx*4;
    uint32_t w[4];
#pragma unroll
    for (int q = 0; q < 4; q++){
        int4 v = s[q];
        w[q] = (v.x != 0 ? 1u : 0u) | (v.y != 0 ? 1u : 0u) << 8
             | (v.z != 0 ? 1u : 0u) << 16 | (v.w != 0 ? 1u : 0u) << 24;
    }
    reinterpret_cast<uint4*>(g_adj8)[idx] = make_uint4(w[0], w[1], w[2], w[3]);
}

// ---------------- K2: H1 = x @ W1^T, fused f1/f2 + per-head max ---------------
// grid (64 rowblocks, NH heads): block covers 64 rows x the head's 64 cols.
__global__ void gemm1_kernel(const float* __restrict__ X, const float* __restrict__ W,
                             const float* __restrict__ A1, const float* __restrict__ A2){
    __shared__ float sx[64][17];
    __shared__ float sw[64][17];
    __shared__ float sa1[64], sa2[64], smaxs[16];
    int tid = threadIdx.x;
    int tx = tid & 15, ty = tid >> 4;
    int mb = blockIdx.x * 64, h = blockIdx.y, nb = h * 64;
    if (tid < 64) sa1[tid] = A1[nb + tid];
    else if (tid < 128) sa2[tid - 64] = A2[nb + tid - 64];
    float acc[4][4] = {};
    for (int kb = 0; kb < ND; kb += 16){
        __syncthreads();
        for (int u = tid; u < 64*16; u += 256){
            int m = u >> 4, k = u & 15;
            sx[m][k] = X[(mb + m)*ND + kb + k];
        }
        for (int u = tid; u < 64*16; u += 256){
            int n = u >> 4, k = u & 15;
            sw[n][k] = W[(nb + n)*ND + kb + k];
        }
        __syncthreads();
#pragma unroll
        for (int k = 0; k < 16; k++){
            float a[4], b[4];
#pragma unroll
            for (int r = 0; r < 4; r++){ a[r] = sx[ty*4 + r][k]; b[r] = sw[tx*4 + r][k]; }
#pragma unroll
            for (int i = 0; i < 4; i++)
#pragma unroll
                for (int j = 0; j < 4; j++) acc[i][j] += a[i]*b[j];
        }
    }
#pragma unroll
    for (int i = 0; i < 4; i++)
#pragma unroll
        for (int j = 0; j < 4; j++)
            g_H1[(mb + ty*4 + i)*ND + nb + tx*4 + j] = acc[i][j];
    // fused f1/f2: reduce over this head's 64 cols (16 tx lanes x 4 each)
    float a1v[4], a2v[4];
#pragma unroll
    for (int j = 0; j < 4; j++){ a1v[j] = sa1[tx*4 + j]; a2v[j] = sa2[tx*4 + j]; }
    float fmax_local = -INFINITY;
#pragma unroll
    for (int i = 0; i < 4; i++){
        float p1 = acc[i][0]*a1v[0] + acc[i][1]*a1v[1] + acc[i][2]*a1v[2] + acc[i][3]*a1v[3];
        float p2 = acc[i][0]*a2v[0] + acc[i][1]*a2v[1] + acc[i][2]*a2v[2] + acc[i][3]*a2v[3];
#pragma unroll
        for (int off = 8; off > 0; off >>= 1){
            p1 += __shfl_down_sync(0xffffffffu, p1, off, 16);
            p2 += __shfl_down_sync(0xffffffffu, p2, off, 16);
        }
        if (tx == 0){
            int row = mb + ty*4 + i;
            g_F1[h*NN + row] = p1;
            g_F2[h*NN + row] = p2;
            fmax_local = fmaxf(fmax_local, p2);
        }
    }
    if (tx == 0) smaxs[ty] = fmax_local;
    __syncthreads();
    if (tid == 0){
        float m = smaxs[0];
#pragma unroll
        for (int k = 1; k < 16; k++) m = fmaxf(m, smaxs[k]);
        atomicMax(&g_f2max1u[h], fenc(m));
    }
}

// ---------------- K3: V fp16 hi/lo + ones column, fused bdf1 ------------------
__global__ void vbf_kernel(){
    int tid = threadIdx.x;            // grid (64, NH), 256 threads
    int jb = blockIdx.x, h = blockIdx.y;
    if (tid < 64){   // fused bdf1 for this 64-j strip
        int j = jb*64 + tid;
        float f2 = g_F2[h*NN + j];
        float d  = f2 - fdec(g_f2max1u[h]);
        g_bdf1[h*NN + j] = make_float4(f2, expf(d), expf(0.01f*d), 0.f);
    }
    int j = jb*64 + (tid >> 2);
    int fg = tid & 3;
    const float4* src = reinterpret_cast<const float4*>(g_H1 + (size_t)j*ND + h*HID + fg*16);
    __half* dhi = g_Vb + (((size_t)(h*2 + 0))*NN + j)*80 + fg*16;
    __half* dlo = g_Vb + (((size_t)(h*2 + 1))*NN + j)*80 + fg*16;
    uint32_t ph[8], pl[8];
#pragma unroll
    for (int q = 0; q < 4; q++){
        float4 v = src[q];
        float e[4] = {v.x, v.y, v.z, v.w};
        __half hh[4], ll[4];
#pragma unroll
        for (int k = 0; k < 4; k++){
            hh[k] = __float2half_rn(e[k]);
            ll[k] = __float2half_rn(e[k] - __half2float(hh[k]));
        }
        ph[q*2]   = packh(hh[0], hh[1]); ph[q*2+1] = packh(hh[2], hh[3]);
        pl[q*2]   = packh(ll[0], ll[1]); pl[q*2+1] = packh(ll[2], ll[3]);
    }
    uint4* oh = reinterpret_cast<uint4*>(dhi);
    uint4* ol = reinterpret_cast<uint4*>(dlo);
    oh[0] = make_uint4(ph[0],ph[1],ph[2],ph[3]);
    oh[1] = make_uint4(ph[4],ph[5],ph[6],ph[7]);
    ol[0] = make_uint4(pl[0],pl[1],pl[2],pl[3]);
    ol[1] = make_uint4(pl[4],pl[5],pl[6],pl[7]);
    if (fg == 3){
        uint4* zh = reinterpret_cast<uint4*>(dhi + 16);
        uint4* zl = reinterpret_cast<uint4*>(dlo + 16);
        zh[0] = make_uint4(0x00003C00u, 0u, 0u, 0u);
        zh[1] = make_uint4(0u, 0u, 0u, 0u);
        zl[0] = make_uint4(0u, 0u, 0u, 0u);
        zl[1] = make_uint4(0u, 0u, 0u, 0u);
    }
}

// ---------------- K4: attn1 wmma fp16 (proven 128-thread config) --------------
__global__ void __launch_bounds__(128) attn1_wmma_kernel(){
    __shared__ __align__(16) unsigned char smem[36864];
    __half* sAh = (__half*)(smem);             // [64][64] 8KB
    __half* sAl = (__half*)(smem + 8192);      // 8KB
    __half* sBh = (__half*)(smem + 16384);     // [64][80] 10KB
    __half* sBl = (__half*)(smem + 26624);     // 10KB
    float*  sepi = (float*)smem;               // epilogue [64][80] 20KB (reuse)
    __shared__ float sf2[64], sBv[64], sDv[64];

    int tid = threadIdx.x;
    int wid = tid >> 5;
    int row0 = blockIdx.x * 64;
    int h = blockIdx.y;
    int r = tid >> 1, jg = tid & 1;

    float f1 = g_F1[h*NN + row0 + r];
    float tt = f1 + fdec(g_f2max1u[h]);
    float M  = tt > 0.f ? tt : 0.01f*tt;
    float alpha = expf(tt - M), beta = expf(0.01f*tt - M);

    wmma::fragment<wmma::accumulator,16,16,16,float> G[5];
#pragma unroll
    for (int nt = 0; nt < 5; nt++) wmma::fill_fragment(G[nt], 0.f);

    const __half* Vh = g_Vb + ((size_t)(h*2 + 0))*NN*80;
    const __half* Vl = g_Vb + ((size_t)(h*2 + 1))*NN*80;
    const uint8_t* adjrow = g_adj8 + (size_t)(row0 + r)*NN;

    for (int t = 0; t < 64; t++){
        int j0 = t * 64;
        __syncthreads();
        if (tid < 64){
            float4 b = g_bdf1[h*NN + j0 + tid];
            sf2[tid] = b.x; sBv[tid] = b.y; sDv[tid] = b.z;
        }
        {   // stage B tile: 64 rows x 80 halves, hi+lo
            int j = tid >> 1, ch = (tid & 1)*40;
            const uint4* srch = reinterpret_cast<const uint4*>(Vh + (size_t)(j0 + j)*80 + ch);
            const uint4* srcl = reinterpret_cast<const uint4*>(Vl + (size_t)(j0 + j)*80 + ch);
            uint4* dsth = reinterpret_cast<uint4*>(sBh + j*80 + ch);
            uint4* dstl = reinterpret_cast<uint4*>(sBl + j*80 + ch);
#pragma unroll
            for (int q = 0; q < 5; q++){ dsth[q] = srch[q]; dstl[q] = srcl[q]; }
        }
        __syncthreads();
        // ---- phase A: 32 weights per thread ----
        uint4 a0 = *reinterpret_cast<const uint4*>(adjrow + j0 + jg*32);
        uint4 a1 = *reinterpret_cast<const uint4*>(adjrow + j0 + jg*32 + 16);
        uint32_t aw[8] = {a0.x, a0.y, a0.z, a0.w, a1.x, a1.y, a1.z, a1.w};
        uint32_t oh[16], ol[16];
#pragma unroll
        for (int p = 0; p < 16; p++){
            uint32_t hw[2], lw[2];
#pragma unroll
            for (int e = 0; e < 2; e++){
                int jl = 2*p + e;
                int jj = jg*32 + jl;
                uint32_t byte = (aw[jl >> 2] >> ((jl & 3)*8)) & 0xFFu;
                float s = f1 + sf2[jj];
                float w = s > 0.f ? alpha*sBv[jj] : beta*sDv[jj];
                if ((byte == 0u) | (s == 0.f)) w = 0.f;
                __half whf = __float2half_rn(w);
                __half wlf = __float2half_rn(w - __half2float(whf));
                hw[e] = __half_as_ushort(whf);
                lw[e] = __half_as_ushort(wlf);
            }
            oh[p] = hw[0] | (hw[1] << 16);
            ol[p] = lw[0] | (lw[1] << 16);
        }
        {
            uint4* dh = reinterpret_cast<uint4*>(sAh + r*64 + jg*32);
            uint4* dl = reinterpret_cast<uint4*>(sAl + r*64 + jg*32);
#pragma unroll
            for (int k = 0; k < 4; k++){
                dh[k] = make_uint4(oh[4*k], oh[4*k+1], oh[4*k+2], oh[4*k+3]);
                dl[k] = make_uint4(ol[4*k], ol[4*k+1], ol[4*k+2], ol[4*k+3]);
            }
        }
        __syncthreads();
        // ---- phase B ----
#pragma unroll
        for (int ks = 0; ks < 4; ks++){
            wmma::fragment<wmma::matrix_a,16,16,16,__half,wmma::row_major> ah, al;
            wmma::load_matrix_sync(ah, sAh + wid*16*64 + ks*16, 64);
            wmma::load_matrix_sync(al, sAl + wid*16*64 + ks*16, 64);
#pragma unroll
            for (int nt = 0; nt < 5; nt++){
                wmma::fragment<wmma::matrix_b,16,16,16,__half,wmma::row_major> bh, bl;
                wmma::load_matrix_sync(bh, sBh + ks*16*80 + nt*16, 80);
                wmma::load_matrix_sync(bl, sBl + ks*16*80 + nt*16, 80);
                wmma::mma_sync(G[nt], ah, bh, G[nt]);
                wmma::mma_sync(G[nt], al, bh, G[nt]);
                wmma::mma_sync(G[nt], ah, bl, G[nt]);
            }
        }
    }
    // ---- epilogue ----
    __syncthreads();
#pragma unroll
    for (int nt = 0; nt < 5; nt++)
        wmma::store_matrix_sync(sepi + wid*16*80 + nt*16, G[nt], 80, wmma::mem_row_major);
    __syncthreads();
    float rz = 1.f / sepi[r*80 + 64];
    float* dst = g_H2 + (size_t)(row0 + r)*ND + h*HID + jg*32;
#pragma unroll
    for (int c = 0; c < 32; c += 4){
        float o[4];
#pragma unroll
        for (int e = 0; e < 4; e++){
            float v = sepi[r*80 + jg*32 + c + e] * rz;
            o[e] = v > 0.f ? v : expm1f(v);
        }
        *reinterpret_cast<float4*>(dst + c) = make_float4(o[0], o[1], o[2], o[3]);
    }
}

// ---------------- K5: G2 = H2 @ W2^T + f-vectors + fused max ------------------
__global__ void gemm2_kernel(const float* __restrict__ W2,
                             const float* __restrict__ a1, const float* __restrict__ a2){
    __shared__ float sW[16][257];
    __shared__ float sa1[16], sa2[16];
    __shared__ float s_u2[16];
    int tid = threadIdx.x;
    for (int u = tid; u < 16*256; u += 256) sW[u >> 8][u & 255] = W2[u];
    if (tid < 16){ sa1[tid] = a1[tid]; sa2[tid] = a2[tid]; }
    __syncthreads();
    int idx = blockIdx.x*256 + tid;
    int i = idx >> 4, c = idx & 15;
    const float4* hr = reinterpret_cast<const float4*>(g_H2 + i*ND);
    float acc = 0.f;
#pragma unroll 4
    for (int k4 = 0; k4 < 64; k4++){
        float4 v = hr[k4];
        acc += v.x*sW[c][k4*4] + v.y*sW[c][k4*4+1] + v.z*sW[c][k4*4+2] + v.w*sW[c][k4*4+3];
    }
    g_G2[idx] = acc;
    float u1 = acc*sa1[c], u2 = acc*sa2[c];
#pragma unroll
    for (int off = 8; off > 0; off >>= 1){
        u1 += __shfl_down_sync(0xffffffffu, u1, off, 16);
        u2 += __shfl_down_sync(0xffffffffu, u2, off, 16);
    }
    if (c == 0){ g_f1b[i] = u1; g_f2b[i] = u2; s_u2[tid >> 4] = u2; }
    __syncthreads();
    if (tid == 0){
        float m = s_u2[0];
#pragma unroll
        for (int k = 1; k < 16; k++) m = fmaxf(m, s_u2[k]);
        atomicMax(g_f2max2u, fenc(m));
    }
}

// ---------------- K6: bdf2 + G2 fp16 hi/lo split ------------------------------
__global__ void bdf2g2_kernel(){
    int row = blockIdx.x*256 + threadIdx.x;   // grid 16
    float f2 = g_f2b[row];
    float d  = f2 - fdec(g_f2max2u[0]);
    g_bdf2[row] = make_float4(f2, expf(d), expf(0.01f*d), 0.f);

    const float4* src = reinterpret_cast<const float4*>(g_G2 + row*NC);
    uint32_t ph[16], pl[16];
#pragma unroll
    for (int q = 0; q < 4; q++){
        float4 v = src[q];
        float e[4] = {v.x, v.y, v.z, v.w};
        __half hh[4], ll[4];
#pragma unroll
        for (int k = 0; k < 4; k++){
            hh[k] = __float2half_rn(e[k]);
            ll[k] = __float2half_rn(e[k] - __half2float(hh[k]));
        }
        ph[q*2]   = packh(hh[0], hh[1]); ph[q*2+1] = packh(hh[2], hh[3]);
        pl[q*2]   = packh(ll[0], ll[1]); pl[q*2+1] = packh(ll[2], ll[3]);
    }
    ph[8] = 0x00003C00u; pl[8] = 0u;
#pragma unroll
    for (int k = 9; k < 16; k++){ ph[k] = 0u; pl[k] = 0u; }
    uint4* dh = reinterpret_cast<uint4*>(g_G2b + ((size_t)0*NN + row)*32);
    uint4* dl = reinterpret_cast<uint4*>(g_G2b + ((size_t)1*NN + row)*32);
#pragma unroll
    for (int k = 0; k < 4; k++){
        dh[k] = make_uint4(ph[4*k], ph[4*k+1], ph[4*k+2], ph[4*k+3]);
        dl[k] = make_uint4(pl[4*k], pl[4*k+1], pl[4*k+2], pl[4*k+3]);
    }
}

// ---------------- K7: attn2 wmma (proven 128-thread config) -------------------
__global__ void __launch_bounds__(128) attn2_wmma_kernel(float* __restrict__ out){
    __shared__ __align__(16) unsigned char smem[24576];
    __half* sAh = (__half*)(smem);             // [64][64] 8KB
    __half* sAl = (__half*)(smem + 8192);      // 8KB
    __half* sBh = (__half*)(smem + 16384);     // [64][32] 4KB
    __half* sBl = (__half*)(smem + 20480);     // 4KB
    float*  sepi = (float*)smem;               // [64][32] 8KB (reuse)
    __shared__ float sf2[64], sBv[64], sDv[64];

    int tid = threadIdx.x;
    int wid = tid >> 5;
    int row0 = blockIdx.x * 64;
    int r = tid >> 1, jg = tid & 1;

    float f1 = g_f1b[row0 + r];
    float tt = f1 + fdec(g_f2max2u[0]);
    float M  = tt > 0.f ? tt : 0.01f*tt;
    float alpha = expf(tt - M), beta = expf(0.01f*tt - M);

    wmma::fragment<wmma::accumulator,16,16,16,float> G[2];
    wmma::fill_fragment(G[0], 0.f);
    wmma::fill_fragment(G[1], 0.f);

    const uint8_t* adjrow = g_adj8 + (size_t)(row0 + r)*NN;

    for (int t = 0; t < 64; t++){
        int j0 = t * 64;
        __syncthreads();
        if (tid < 64){
            float4 b = g_bdf2[j0 + tid];
            sf2[tid] = b.x; sBv[tid] = b.y; sDv[tid] = b.z;
        }
        {   // stage B: 64 rows x 32 halves, hi+lo
            int j = tid >> 1, part = tid & 1;
            const uint4* src = reinterpret_cast<const uint4*>(
                g_G2b + ((size_t)part*NN + j0 + j)*32);
            uint4* dst = reinterpret_cast<uint4*>((part ? sBl : sBh) + j*32);
#pragma unroll
            for (int q = 0; q < 4; q++) dst[q] = src[q];
        }
        __syncthreads();
        uint4 a0 = *reinterpret_cast<const uint4*>(adjrow + j0 + jg*32);
        uint4 a1 = *reinterpret_cast<const uint4*>(adjrow + j0 + jg*32 + 16);
        uint32_t aw[8] = {a0.x, a0.y, a0.z, a0.w, a1.x, a1.y, a1.z, a1.w};
        uint32_t oh[16], ol[16];
#pragma unroll
        for (int p = 0; p < 16; p++){
            uint32_t hw[2], lw[2];
#pragma unroll
            for (int e = 0; e < 2; e++){
                int jl = 2*p + e;
                int jj = jg*32 + jl;
                uint32_t byte = (aw[jl >> 2] >> ((jl & 3)*8)) & 0xFFu;
                float s = f1 + sf2[jj];
                float w = s > 0.f ? alpha*sBv[jj] : beta*sDv[jj];
                if ((byte == 0u) | (s == 0.f)) w = 0.f;
                __half whf = __float2half_rn(w);
                __half wlf = __float2half_rn(w - __half2float(whf));
                hw[e] = __half_as_ushort(whf);
                lw[e] = __half_as_ushort(wlf);
            }
            oh[p] = hw[0] | (hw[1] << 16);
            ol[p] = lw[0] | (lw[1] << 16);
        }
        {
            uint4* dh = reinterpret_cast<uint4*>(sAh + r*64 + jg*32);
            uint4* dl = reinterpret_cast<uint4*>(sAl + r*64 + jg*32);
#pragma unroll
            for (int k = 0; k < 4; k++){
                dh[k] = make_uint4(oh[4*k], oh[4*k+1], oh[4*k+2], oh[4*k+3]);
                dl[k] = make_uint4(ol[4*k], ol[4*k+1], ol[4*k+2], ol[4*k+3]);
            }
        }
        __syncthreads();
#pragma unroll
        for (int ks = 0; ks < 4; ks++){
            wmma::fragment<wmma::matrix_a,16,16,16,__half,wmma::row_major> ah, al;
            wmma::load_matrix_sync(ah, sAh + wid*16*64 + ks*16, 64);
            wmma::load_matrix_sync(al, sAl + wid*16*64 + ks*16, 64);
#pragma unroll
            for (int nt = 0; nt < 2; nt++){
                wmma::fragment<wmma::matrix_b,16,16,16,__half,wmma::row_major> bh, bl;
                wmma::load_matrix_sync(bh, sBh + ks*16*32 + nt*16, 32);
                wmma::load_matrix_sync(bl, sBl + ks*16*32 + nt*16, 32);
                wmma::mma_sync(G[nt], ah, bh, G[nt]);
                wmma::mma_sync(G[nt], al, bh, G[nt]);
                wmma::mma_sync(G[nt], ah, bl, G[nt]);
            }
        }
    }
    __syncthreads();
    wmma::store_matrix_sync(sepi + wid*16*32,      G[0], 32, wmma::mem_row_major);
    wmma::store_matrix_sync(sepi + wid*16*32 + 16, G[1], 32, wmma::mem_row_major);
    __syncthreads();
    float rz = 1.f / sepi[r*32 + 16];
    float* dst = out + (size_t)(row0 + r)*NC + jg*8;
#pragma unroll
    for (int c = 0; c < 8; c += 4){
        float o[4];
#pragma unroll
        for (int e = 0; e < 4; e++) o[e] = sepi[r*32 + jg*8 + c + e] * rz;
        *reinterpret_cast<float4*>(dst + c) = make_float4(o[0], o[1], o[2], o[3]);
    }
}

// ---------------- launch ------------------------------------------------------
extern "C" void kernel_launch(void* const* d_in, const int* in_sizes, int n_in,
                              void* d_out, int out_size){
    const float* x    = (const float*)d_in[0];
    const int*   adj  = (const int*)  d_in[1];
    const float* W1   = (const float*)d_in[2];
    const float* a1_1 = (const float*)d_in[3];
    const float* a2_1 = (const float*)d_in[4];
    const float* W2   = (const float*)d_in[5];
    const float* a1_2 = (const float*)d_in[6];
    const float* a2_2 = (const float*)d_in[7];
    float* out = (float*)d_out;

    init_kernel<<<1, 32>>>();
    adj8_kernel<<<4096, 256>>>(adj);
    gemm1_kernel<<<dim3(64, NH), 256>>>(x, W1, a1_1, a2_1);
    vbf_kernel<<<dim3(64, NH), 256>>>();
    attn1_wmma_kernel<<<dim3(64, NH), 128>>>();
    gemm2_kernel<<<256, 256>>>(W2, a1_2, a2_2);
    bdf2g2_kernel<<<16, 256>>>();
    attn2_wmma_kernel<<<64, 128>>>(out);
}

// round 10
// speedup vs baseline: 1.5374x; 1.2560x over previous
#include <cuda_runtime.h>
#include <cuda_fp16.h>
#include <mma.h>
#include <math.h>
#include <stdint.h>

using namespace nvcuda;

#define NN 4096
#define ND 256
#define HID 64
#define NH 4
#define NC 16

// ---------------- scratch (static device globals) ---------------------------
__device__ float  g_H1[NN*ND];
__device__ float  g_F1[NH*NN];
__device__ float  g_F2[NH*NN];
__device__ unsigned g_f2max1u[NH];
__device__ float4 g_bdf1[NH*NN];
__device__ uint8_t g_adj8[(size_t)NN*NN];
__device__ __half g_Vb[(size_t)NH*2*NN*80];  // [head][hi|lo][j][80] (col64 = ones)
__device__ float  g_H2[NN*ND];
__device__ float  g_G2[NN*NC];
__device__ __half g_G2b[2*NN*32];            // [hi|lo][j][32] (col16 = ones)
__device__ float  g_f1b[NN];
__device__ float  g_f2b[NN];
__device__ unsigned g_f2max2u[1];
__device__ float4 g_bdf2[NN];

// ---------------- helpers -----------------------------------------------------
__device__ __forceinline__ unsigned fenc(float f){
    unsigned u = __float_as_uint(f);
    return (u & 0x80000000u) ? ~u : (u | 0x80000000u);
}
__device__ __forceinline__ float fdec(unsigned u){
    return (u & 0x80000000u) ? __uint_as_float(u ^ 0x80000000u) : __uint_as_float(~u);
}
__device__ __forceinline__ uint32_t packh(__half a, __half b){
    return (uint32_t)__half_as_ushort(a) | ((uint32_t)__half_as_ushort(b) << 16);
}
__device__ __forceinline__ uint32_t pack2f(float a, float b){
    __half2 h = __floats2half2_rn(a, b);
    return *reinterpret_cast<uint32_t*>(&h);
}

// ---------------- K0: init atomic-max cells -----------------------------------
__global__ void init_kernel(){
    int t = threadIdx.x;
    if (t < NH) g_f2max1u[t] = 0u;
    if (t == NH) g_f2max2u[0] = 0u;
}

// ---------------- K1: adjacency -> bytes --------------------------------------
__global__ void adj8_kernel(const int* __restrict__ adj){
    size_t idx = (size_t)blockIdx.x*256 + threadIdx.x;   // grid 4096
    const int4* s = reinterpret_cast<const int4*>(adj) + idx*4;
    uint32_t w[4];
#pragma unroll
    for (int q = 0; q < 4; q++){
        int4 v = s[q];
        w[q] = (v.x != 0 ? 1u : 0u) | (v.y != 0 ? 1u : 0u) << 8
             | (v.z != 0 ? 1u : 0u) << 16 | (v.w != 0 ? 1u : 0u) << 24;
    }
    reinterpret_cast<uint4*>(g_adj8)[idx] = make_uint4(w[0], w[1], w[2], w[3]);
}

// ---------------- K2: H1 = x @ W1^T, fused f1/f2 + per-head max ---------------
__global__ void gemm1_kernel(const float* __restrict__ X, const float* __restrict__ W,
                             const float* __restrict__ A1, const float* __restrict__ A2){
    __shared__ float sx[64][17];
    __shared__ float sw[64][17];
    __shared__ float sa1[64], sa2[64], smaxs[16];
    int tid = threadIdx.x;
    int tx = tid & 15, ty = tid >> 4;
    int mb = blockIdx.x * 64, h = blockIdx.y, nb = h * 64;
    if (tid < 64) sa1[tid] = A1[nb + tid];
    else if (tid < 128) sa2[tid - 64] = A2[nb + tid - 64];
    float acc[4][4] = {};
    for (int kb = 0; kb < ND; kb += 16){
        __syncthreads();
        for (int u = tid; u < 64*16; u += 256){
            int m = u >> 4, k = u & 15;
            sx[m][k] = X[(mb + m)*ND + kb + k];
        }
        for (int u = tid; u < 64*16; u += 256){
            int n = u >> 4, k = u & 15;
            sw[n][k] = W[(nb + n)*ND + kb + k];
        }
        __syncthreads();
#pragma unroll
        for (int k = 0; k < 16; k++){
            float a[4], b[4];
#pragma unroll
            for (int r = 0; r < 4; r++){ a[r] = sx[ty*4 + r][k]; b[r] = sw[tx*4 + r][k]; }
#pragma unroll
            for (int i = 0; i < 4; i++)
#pragma unroll
                for (int j = 0; j < 4; j++) acc[i][j] += a[i]*b[j];
        }
    }
#pragma unroll
    for (int i = 0; i < 4; i++)
#pragma unroll
        for (int j = 0; j < 4; j++)
            g_H1[(mb + ty*4 + i)*ND + nb + tx*4 + j] = acc[i][j];
    float a1v[4], a2v[4];
#pragma unroll
    for (int j = 0; j < 4; j++){ a1v[j] = sa1[tx*4 + j]; a2v[j] = sa2[tx*4 + j]; }
    float fmax_local = -INFINITY;
#pragma unroll
    for (int i = 0; i < 4; i++){
        float p1 = acc[i][0]*a1v[0] + acc[i][1]*a1v[1] + acc[i][2]*a1v[2] + acc[i][3]*a1v[3];
        float p2 = acc[i][0]*a2v[0] + acc[i][1]*a2v[1] + acc[i][2]*a2v[2] + acc[i][3]*a2v[3];
#pragma unroll
        for (int off = 8; off > 0; off >>= 1){
            p1 += __shfl_down_sync(0xffffffffu, p1, off, 16);
            p2 += __shfl_down_sync(0xffffffffu, p2, off, 16);
        }
        if (tx == 0){
            int row = mb + ty*4 + i;
            g_F1[h*NN + row] = p1;
            g_F2[h*NN + row] = p2;
            fmax_local = fmaxf(fmax_local, p2);
        }
    }
    if (tx == 0) smaxs[ty] = fmax_local;
    __syncthreads();
    if (tid == 0){
        float m = smaxs[0];
#pragma unroll
        for (int k = 1; k < 16; k++) m = fmaxf(m, smaxs[k]);
        atomicMax(&g_f2max1u[h], fenc(m));
    }
}

// ---------------- K3: V fp16 hi/lo + ones column, fused bdf1 ------------------
__global__ void vbf_kernel(){
    int tid = threadIdx.x;            // grid (64, NH), 256 threads
    int jb = blockIdx.x, h = blockIdx.y;
    if (tid < 64){
        int j = jb*64 + tid;
        float f2 = g_F2[h*NN + j];
        float d  = f2 - fdec(g_f2max1u[h]);
        g_bdf1[h*NN + j] = make_float4(f2, expf(d), expf(0.01f*d), 0.f);
    }
    int j = jb*64 + (tid >> 2);
    int fg = tid & 3;
    const float4* src = reinterpret_cast<const float4*>(g_H1 + (size_t)j*ND + h*HID + fg*16);
    __half* dhi = g_Vb + (((size_t)(h*2 + 0))*NN + j)*80 + fg*16;
    __half* dlo = g_Vb + (((size_t)(h*2 + 1))*NN + j)*80 + fg*16;
    uint32_t ph[8], pl[8];
#pragma unroll
    for (int q = 0; q < 4; q++){
        float4 v = src[q];
        float e[4] = {v.x, v.y, v.z, v.w};
        __half hh[4], ll[4];
#pragma unroll
        for (int k = 0; k < 4; k++){
            hh[k] = __float2half_rn(e[k]);
            ll[k] = __float2half_rn(e[k] - __half2float(hh[k]));
        }
        ph[q*2]   = packh(hh[0], hh[1]); ph[q*2+1] = packh(hh[2], hh[3]);
        pl[q*2]   = packh(ll[0], ll[1]); pl[q*2+1] = packh(ll[2], ll[3]);
    }
    uint4* oh = reinterpret_cast<uint4*>(dhi);
    uint4* ol = reinterpret_cast<uint4*>(dlo);
    oh[0] = make_uint4(ph[0],ph[1],ph[2],ph[3]);
    oh[1] = make_uint4(ph[4],ph[5],ph[6],ph[7]);
    ol[0] = make_uint4(pl[0],pl[1],pl[2],pl[3]);
    ol[1] = make_uint4(pl[4],pl[5],pl[6],pl[7]);
    if (fg == 3){
        uint4* zh = reinterpret_cast<uint4*>(dhi + 16);
        uint4* zl = reinterpret_cast<uint4*>(dlo + 16);
        zh[0] = make_uint4(0x00003C00u, 0u, 0u, 0u);
        zh[1] = make_uint4(0u, 0u, 0u, 0u);
        zl[0] = make_uint4(0u, 0u, 0u, 0u);
        zl[1] = make_uint4(0u, 0u, 0u, 0u);
    }
}

// ---------------- phase-A weight producer (shared by both attn kernels) -------
// computes 32 fp16 weights (one row, jg half) -> 4 uint4 at dstA (row stride 64)
__device__ __forceinline__ void produce_row(
    const uint8_t* adjrow_t,          // adjacency row ptr at tile base
    const float4* sbdf,               // 64-entry bdf for this tile
    float f1, float alpha, float beta,
    int jg, __half* dstA, int row)
{
    uint4 a0 = *reinterpret_cast<const uint4*>(adjrow_t + jg*32);
    uint4 a1 = *reinterpret_cast<const uint4*>(adjrow_t + jg*32 + 16);
    uint32_t aw[8] = {a0.x, a0.y, a0.z, a0.w, a1.x, a1.y, a1.z, a1.w};
    uint32_t oh[16];
#pragma unroll
    for (int p = 0; p < 16; p++){
        int jj = jg*32 + 2*p;
        float4 b0 = sbdf[jj], b1 = sbdf[jj + 1];
        float s0 = f1 + b0.x, s1 = f1 + b1.x;
        float t0 = s0 > 0.f ? b0.y : b0.z;
        float t1 = s1 > 0.f ? b1.y : b1.z;
        float c0 = s0 > 0.f ? alpha : beta;
        float c1 = s1 > 0.f ? alpha : beta;
        uint32_t word = aw[p >> 1];
        uint32_t sh = (p & 1) * 16;
        uint32_t b0b = (word >> sh) & 0xFFu;
        uint32_t b1b = (word >> (sh + 8)) & 0xFFu;
        uint32_t z = ((b0b != 0u && s0 != 0.f) ? 0x0000FFFFu : 0u)
                   | ((b1b != 0u && s1 != 0.f) ? 0xFFFF0000u : 0u);
        oh[p] = pack2f(t0*c0, t1*c1) & z;
    }
    uint4* dh = reinterpret_cast<uint4*>(dstA + row*64 + jg*32);
    dh[0] = make_uint4(oh[0], oh[1], oh[2], oh[3]);
    dh[1] = make_uint4(oh[4], oh[5], oh[6], oh[7]);
    dh[2] = make_uint4(oh[8], oh[9], oh[10], oh[11]);
    dh[3] = make_uint4(oh[12], oh[13], oh[14], oh[15]);
}

// ---------------- K4: attn1 pipelined wmma ------------------------------------
// grid (64, NH), 256 threads: warps 0-3 = MMA consumers, 4-7 = A producers.
// dyn smem: AH[2][64][64] 16K | B[2][hi 10240|lo 10240] 40K | bdf[2][64]f4 2K
#define A1_AH(b)  ((__half*)(dsm + (b)*8192))
#define A1_BH(b)  ((__half*)(dsm + 16384 + (b)*20480))
#define A1_BL(b)  ((__half*)(dsm + 16384 + (b)*20480 + 10240))
#define A1_BDF(b) ((float4*)(dsm + 57344 + (b)*1024))
#define A1_TOT    59392

__global__ void __launch_bounds__(256) attn1_wmma_kernel(){
    extern __shared__ __align__(16) unsigned char dsm[];
    float* sepi = (float*)dsm;

    int tid = threadIdx.x;
    int wid = tid >> 5;
    int row0 = blockIdx.x * 64;
    int h = blockIdx.y;
    const __half* Vh = g_Vb + ((size_t)(h*2 + 0))*NN*80;
    const __half* Vl = g_Vb + ((size_t)(h*2 + 1))*NN*80;
    const float4* bdfg = g_bdf1 + h*NN;

    // producer identity
    int tp = tid - 128;
    int prow = tp >> 1, pjg = tp & 1;
    float f1 = 0.f, alpha = 0.f, beta = 0.f;
    const uint8_t* adjrow = nullptr;
    if (tid >= 128){
        f1 = g_F1[h*NN + row0 + prow];
        float tt = f1 + fdec(g_f2max1u[h]);
        float M  = tt > 0.f ? tt : 0.01f*tt;
        alpha = expf(tt - M); beta = expf(0.01f*tt - M);
        adjrow = g_adj8 + (size_t)(row0 + prow)*NN;
    }

    wmma::fragment<wmma::accumulator,16,16,16,float> G[5];
#pragma unroll
    for (int nt = 0; nt < 5; nt++) wmma::fill_fragment(G[nt], 0.f);

    // prologue: bdf(0) -> buf0
    if (tid < 64) A1_BDF(0)[tid] = bdfg[tid];
    __syncthreads();
    // A(0), B(0), bdf(1)
    if (tid >= 128){
        produce_row(adjrow, A1_BDF(0), f1, alpha, beta, pjg, A1_AH(0), prow);
        if (tp < 64) A1_BDF(1)[tp] = bdfg[64 + tp];
    } else {
        int j = tid >> 1, ch = (tid & 1)*40;
        const uint4* sh4 = reinterpret_cast<const uint4*>(Vh + (size_t)j*80 + ch);
        const uint4* sl4 = reinterpret_cast<const uint4*>(Vl + (size_t)j*80 + ch);
        uint4* dh4 = reinterpret_cast<uint4*>(A1_BH(0) + j*80 + ch);
        uint4* dl4 = reinterpret_cast<uint4*>(A1_BL(0) + j*80 + ch);
#pragma unroll
        for (int q = 0; q < 5; q++){ dh4[q] = sh4[q]; dl4[q] = sl4[q]; }
    }
    __syncthreads();

    for (int t = 0; t < 64; t++){
        int p = t & 1;
        if (tid >= 128){
            if (t < 63)
                produce_row(adjrow + (t+1)*64, A1_BDF(p^1), f1, alpha, beta,
                            pjg, A1_AH(p^1), prow);
            if (t < 62 && tp < 64) A1_BDF(p)[tp] = bdfg[(t+2)*64 + tp];
        } else {
            if (t < 63){
                int j = tid >> 1, ch = (tid & 1)*40;
                size_t jb = (size_t)((t+1)*64 + j)*80 + ch;
                const uint4* sh4 = reinterpret_cast<const uint4*>(Vh + jb);
                const uint4* sl4 = reinterpret_cast<const uint4*>(Vl + jb);
                uint4* dh4 = reinterpret_cast<uint4*>(A1_BH(p^1) + j*80 + ch);
                uint4* dl4 = reinterpret_cast<uint4*>(A1_BL(p^1) + j*80 + ch);
#pragma unroll
                for (int q = 0; q < 5; q++){ dh4[q] = sh4[q]; dl4[q] = sl4[q]; }
            }
            const __half* Ab = A1_AH(p) + wid*16*64;
            const __half* Bh = A1_BH(p);
            const __half* Bl = A1_BL(p);
#pragma unroll
            for (int ks = 0; ks < 4; ks++){
                wmma::fragment<wmma::matrix_a,16,16,16,__half,wmma::row_major> ah;
                wmma::load_matrix_sync(ah, Ab + ks*16, 64);
#pragma unroll
                for (int nt = 0; nt < 5; nt++){
                    wmma::fragment<wmma::matrix_b,16,16,16,__half,wmma::row_major> bh, bl;
                    wmma::load_matrix_sync(bh, Bh + ks*16*80 + nt*16, 80);
                    wmma::load_matrix_sync(bl, Bl + ks*16*80 + nt*16, 80);
                    wmma::mma_sync(G[nt], ah, bh, G[nt]);
                    wmma::mma_sync(G[nt], ah, bl, G[nt]);
                }
            }
        }
        __syncthreads();
    }
    // epilogue
    if (wid < 4){
#pragma unroll
        for (int nt = 0; nt < 5; nt++)
            wmma::store_matrix_sync(sepi + wid*16*80 + nt*16, G[nt], 80, wmma::mem_row_major);
    }
    __syncthreads();
    {
        int r = tid >> 2, cg = (tid & 3)*16;
        float rz = 1.f / sepi[r*80 + 64];
        float* dst = g_H2 + (size_t)(row0 + r)*ND + h*HID + cg;
#pragma unroll
        for (int c = 0; c < 16; c += 4){
            float o[4];
#pragma unroll
            for (int e = 0; e < 4; e++){
                float v = sepi[r*80 + cg + c + e] * rz;
                o[e] = v > 0.f ? v : expm1f(v);
            }
            *reinterpret_cast<float4*>(dst + c) = make_float4(o[0], o[1], o[2], o[3]);
        }
    }
}

// ---------------- K5: G2 = H2 @ W2^T + f-vectors + fused max ------------------
__global__ void gemm2_kernel(const float* __restrict__ W2,
                             const float* __restrict__ a1, const float* __restrict__ a2){
    __shared__ float sW[16][257];
    __shared__ float sa1[16], sa2[16];
    __shared__ float s_u2[16];
    int tid = threadIdx.x;
    for (int u = tid; u < 16*256; u += 256) sW[u >> 8][u & 255] = W2[u];
    if (tid < 16){ sa1[tid] = a1[tid]; sa2[tid] = a2[tid]; }
    __syncthreads();
    int idx = blockIdx.x*256 + tid;
    int i = idx >> 4, c = idx & 15;
    const float4* hr = reinterpret_cast<const float4*>(g_H2 + i*ND);
    float acc = 0.f;
#pragma unroll 4
    for (int k4 = 0; k4 < 64; k4++){
        float4 v = hr[k4];
        acc += v.x*sW[c][k4*4] + v.y*sW[c][k4*4+1] + v.z*sW[c][k4*4+2] + v.w*sW[c][k4*4+3];
    }
    g_G2[idx] = acc;
    float u1 = acc*sa1[c], u2 = acc*sa2[c];
#pragma unroll
    for (int off = 8; off > 0; off >>= 1){
        u1 += __shfl_down_sync(0xffffffffu, u1, off, 16);
        u2 += __shfl_down_sync(0xffffffffu, u2, off, 16);
    }
    if (c == 0){ g_f1b[i] = u1; g_f2b[i] = u2; s_u2[tid >> 4] = u2; }
    __syncthreads();
    if (tid == 0){
        float m = s_u2[0];
#pragma unroll
        for (int k = 1; k < 16; k++) m = fmaxf(m, s_u2[k]);
        atomicMax(g_f2max2u, fenc(m));
    }
}

// ---------------- K6: bdf2 + G2 fp16 hi/lo split ------------------------------
__global__ void bdf2g2_kernel(){
    int row = blockIdx.x*256 + threadIdx.x;   // grid 16
    float f2 = g_f2b[row];
    float d  = f2 - fdec(g_f2max2u[0]);
    g_bdf2[row] = make_float4(f2, expf(d), expf(0.01f*d), 0.f);

    const float4* src = reinterpret_cast<const float4*>(g_G2 + row*NC);
    uint32_t ph[16], pl[16];
#pragma unroll
    for (int q = 0; q < 4; q++){
        float4 v = src[q];
        float e[4] = {v.x, v.y, v.z, v.w};
        __half hh[4], ll[4];
#pragma unroll
        for (int k = 0; k < 4; k++){
            hh[k] = __float2half_rn(e[k]);
            ll[k] = __float2half_rn(e[k] - __half2float(hh[k]));
        }
        ph[q*2]   = packh(hh[0], hh[1]); ph[q*2+1] = packh(hh[2], hh[3]);
        pl[q*2]   = packh(ll[0], ll[1]); pl[q*2+1] = packh(ll[2], ll[3]);
    }
    ph[8] = 0x00003C00u; pl[8] = 0u;
#pragma unroll
    for (int k = 9; k < 16; k++){ ph[k] = 0u; pl[k] = 0u; }
    uint4* dh = reinterpret_cast<uint4*>(g_G2b + ((size_t)0*NN + row)*32);
    uint4* dl = reinterpret_cast<uint4*>(g_G2b + ((size_t)1*NN + row)*32);
#pragma unroll
    for (int k = 0; k < 4; k++){
        dh[k] = make_uint4(ph[4*k], ph[4*k+1], ph[4*k+2], ph[4*k+3]);
        dl[k] = make_uint4(pl[4*k], pl[4*k+1], pl[4*k+2], pl[4*k+3]);
    }
}

// ---------------- K7: attn2 pipelined wmma -> logits --------------------------
// grid 64, 256 threads. Static smem 34816 B.
#define A2_AH(b)  ((__half*)(smem2 + (b)*8192))
#define A2_BH(b)  ((__half*)(smem2 + 16384 + (b)*8192))
#define A2_BL(b)  ((__half*)(smem2 + 16384 + (b)*8192 + 4096))
#define A2_BDF(b) ((float4*)(smem2 + 32768 + (b)*1024))

__global__ void __launch_bounds__(256) attn2_wmma_kernel(float* __restrict__ out){
    __shared__ __align__(16) unsigned char smem2[34816];
    float* sepi = (float*)smem2;

    int tid = threadIdx.x;
    int wid = tid >> 5;
    int row0 = blockIdx.x * 64;

    int tp = tid - 128;
    int prow = tp >> 1, pjg = tp & 1;
    float f1 = 0.f, alpha = 0.f, beta = 0.f;
    const uint8_t* adjrow = nullptr;
    if (tid >= 128){
        f1 = g_f1b[row0 + prow];
        float tt = f1 + fdec(g_f2max2u[0]);
        float M  = tt > 0.f ? tt : 0.01f*tt;
        alpha = expf(tt - M); beta = expf(0.01f*tt - M);
        adjrow = g_adj8 + (size_t)(row0 + prow)*NN;
    }

    wmma::fragment<wmma::accumulator,16,16,16,float> G[2];
    wmma::fill_fragment(G[0], 0.f);
    wmma::fill_fragment(G[1], 0.f);

    if (tid < 64) A2_BDF(0)[tid] = g_bdf2[tid];
    __syncthreads();
    if (tid >= 128){
        produce_row(adjrow, A2_BDF(0), f1, alpha, beta, pjg, A2_AH(0), prow);
        if (tp < 64) A2_BDF(1)[tp] = g_bdf2[64 + tp];
    } else {
        int j = tid >> 1, part = tid & 1;
        const uint4* src = reinterpret_cast<const uint4*>(g_G2b + ((size_t)part*NN + j)*32);
        uint4* dst = reinterpret_cast<uint4*>((part ? A2_BL(0) : A2_BH(0)) + j*32);
#pragma unroll
        for (int q = 0; q < 4; q++) dst[q] = src[q];
    }
    __syncthreads();

    for (int t = 0; t < 64; t++){
        int p = t & 1;
        if (tid >= 128){
            if (t < 63)
                produce_row(adjrow + (t+1)*64, A2_BDF(p^1), f1, alpha, beta,
                            pjg, A2_AH(p^1), prow);
            if (t < 62 && tp < 64) A2_BDF(p)[tp] = g_bdf2[(t+2)*64 + tp];
        } else {
            if (t < 63){
                int j = tid >> 1, part = tid & 1;
                const uint4* src = reinterpret_cast<const uint4*>(
                    g_G2b + ((size_t)part*NN + (t+1)*64 + j)*32);
                uint4* dst = reinterpret_cast<uint4*>(
                    (part ? A2_BL(p^1) : A2_BH(p^1)) + j*32);
#pragma unroll
                for (int q = 0; q < 4; q++) dst[q] = src[q];
            }
            const __half* Ab = A2_AH(p) + wid*16*64;
            const __half* Bh = A2_BH(p);
            const __half* Bl = A2_BL(p);
#pragma unroll
            for (int ks = 0; ks < 4; ks++){
                wmma::fragment<wmma::matrix_a,16,16,16,__half,wmma::row_major> ah;
                wmma::load_matrix_sync(ah, Ab + ks*16, 64);
#pragma unroll
                for (int nt = 0; nt < 2; nt++){
                    wmma::fragment<wmma::matrix_b,16,16,16,__half,wmma::row_major> bh, bl;
                    wmma::load_matrix_sync(bh, Bh + ks*16*32 + nt*16, 32);
                    wmma::load_matrix_sync(bl, Bl + ks*16*32 + nt*16, 32);
                    wmma::mma_sync(G[nt], ah, bh, G[nt]);
                    wmma::mma_sync(G[nt], ah, bl, G[nt]);
                }
            }
        }
        __syncthreads();
    }
    if (wid < 4){
        wmma::store_matrix_sync(sepi + wid*16*32,      G[0], 32, wmma::mem_row_major);
        wmma::store_matrix_sync(sepi + wid*16*32 + 16, G[1], 32, wmma::mem_row_major);
    }
    __syncthreads();
    {
        int r = tid >> 2, cg = (tid & 3)*4;
        float rz = 1.f / sepi[r*32 + 16];
        float o[4];
#pragma unroll
        for (int e = 0; e < 4; e++) o[e] = sepi[r*32 + cg + e] * rz;
        *reinterpret_cast<float4*>(out + (size_t)(row0 + r)*NC + cg)
            = make_float4(o[0], o[1], o[2], o[3]);
    }
}

// ---------------- launch ------------------------------------------------------
extern "C" void kernel_launch(void* const* d_in, const int* in_sizes, int n_in,
                              void* d_out, int out_size){
    const float* x    = (const float*)d_in[0];
    const int*   adj  = (const int*)  d_in[1];
    const float* W1   = (const float*)d_in[2];
    const float* a1_1 = (const float*)d_in[3];
    const float* a2_1 = (const float*)d_in[4];
    const float* W2   = (const float*)d_in[5];
    const float* a1_2 = (const float*)d_in[6];
    const float* a2_2 = (const float*)d_in[7];
    float* out = (float*)d_out;

    static int smem_set = 0;
    if (!smem_set){
        cudaFuncSetAttribute(attn1_wmma_kernel,
                             cudaFuncAttributeMaxDynamicSharedMemorySize, A1_TOT);
        smem_set = 1;
    }

    init_kernel<<<1, 32>>>();
    adj8_kernel<<<4096, 256>>>(adj);
    gemm1_kernel<<<dim3(64, NH), 256>>>(x, W1, a1_1, a2_1);
    vbf_kernel<<<dim3(64, NH), 256>>>();
    attn1_wmma_kernel<<<dim3(64, NH), 256, A1_TOT>>>();
    gemm2_kernel<<<256, 256>>>(W2, a1_2, a2_2);
    bdf2g2_kernel<<<16, 256>>>();
    attn2_wmma_kernel<<<64, 256>>>(out);
}

// round 11
// speedup vs baseline: 1.8278x; 1.1889x over previous
#include <cuda_runtime.h>
#include <cuda_fp16.h>
#include <mma.h>
#include <math.h>
#include <stdint.h>

using namespace nvcuda;

#define NN 4096
#define ND 256
#define HID 64
#define NH 4
#define NC 16

// ---------------- scratch (static device globals) ---------------------------
__device__ float  g_H1[NN*ND];
__device__ float  g_F1[NH*NN];
__device__ float  g_F2[NH*NN];
__device__ unsigned g_f2max1u[NH];
__device__ float4 g_bdf1[NH*NN];
__device__ uint8_t g_adj8[(size_t)NN*NN];
__device__ __half g_Vb[(size_t)NH*NN*80];    // [head][j][80] hi only (col64 = ones)
__device__ float  g_H2[NN*ND];
__device__ float  g_G2[NN*NC];
__device__ __half g_G2b[NN*32];              // [j][32] hi only (col16 = ones)
__device__ float  g_f1b[NN];
__device__ float  g_f2b[NN];
__device__ unsigned g_f2max2u[1];
__device__ float4 g_bdf2[NN];

// ---------------- helpers -----------------------------------------------------
__device__ __forceinline__ unsigned fenc(float f){
    unsigned u = __float_as_uint(f);
    return (u & 0x80000000u) ? ~u : (u | 0x80000000u);
}
__device__ __forceinline__ float fdec(unsigned u){
    return (u & 0x80000000u) ? __uint_as_float(u ^ 0x80000000u) : __uint_as_float(~u);
}
__device__ __forceinline__ uint32_t packh(__half a, __half b){
    return (uint32_t)__half_as_ushort(a) | ((uint32_t)__half_as_ushort(b) << 16);
}
__device__ __forceinline__ uint32_t pack2f(float a, float b){
    __half2 h = __floats2half2_rn(a, b);
    return *reinterpret_cast<uint32_t*>(&h);
}

// ---------------- K0: init atomic-max cells -----------------------------------
__global__ void init_kernel(){
    int t = threadIdx.x;
    if (t < NH) g_f2max1u[t] = 0u;
    if (t == NH) g_f2max2u[0] = 0u;
}

// ---------------- K1: adjacency -> bytes --------------------------------------
__global__ void adj8_kernel(const int* __restrict__ adj){
    size_t idx = (size_t)blockIdx.x*256 + threadIdx.x;   // grid 4096
    const int4* s = reinterpret_cast<const int4*>(adj) + idx*4;
    uint32_t w[4];
#pragma unroll
    for (int q = 0; q < 4; q++){
        int4 v = s[q];
        w[q] = (v.x != 0 ? 1u : 0u) | (v.y != 0 ? 1u : 0u) << 8
             | (v.z != 0 ? 1u : 0u) << 16 | (v.w != 0 ? 1u : 0u) << 24;
    }
    reinterpret_cast<uint4*>(g_adj8)[idx] = make_uint4(w[0], w[1], w[2], w[3]);
}

// ---------------- K2: H1 = x @ W1^T, fused f1/f2 + per-head max ---------------
__global__ void gemm1_kernel(const float* __restrict__ X, const float* __restrict__ W,
                             const float* __restrict__ A1, const float* __restrict__ A2){
    __shared__ float sx[64][17];
    __shared__ float sw[64][17];
    __shared__ float sa1[64], sa2[64], smaxs[16];
    int tid = threadIdx.x;
    int tx = tid & 15, ty = tid >> 4;
    int mb = blockIdx.x * 64, h = blockIdx.y, nb = h * 64;
    if (tid < 64) sa1[tid] = A1[nb + tid];
    else if (tid < 128) sa2[tid - 64] = A2[nb + tid - 64];
    float acc[4][4] = {};
    for (int kb = 0; kb < ND; kb += 16){
        __syncthreads();
        for (int u = tid; u < 64*16; u += 256){
            int m = u >> 4, k = u & 15;
            sx[m][k] = X[(mb + m)*ND + kb + k];
        }
        for (int u = tid; u < 64*16; u += 256){
            int n = u >> 4, k = u & 15;
            sw[n][k] = W[(nb + n)*ND + kb + k];
        }
        __syncthreads();
#pragma unroll
        for (int k = 0; k < 16; k++){
            float a[4], b[4];
#pragma unroll
            for (int r = 0; r < 4; r++){ a[r] = sx[ty*4 + r][k]; b[r] = sw[tx*4 + r][k]; }
#pragma unroll
            for (int i = 0; i < 4; i++)
#pragma unroll
                for (int j = 0; j < 4; j++) acc[i][j] += a[i]*b[j];
        }
    }
#pragma unroll
    for (int i = 0; i < 4; i++)
#pragma unroll
        for (int j = 0; j < 4; j++)
            g_H1[(mb + ty*4 + i)*ND + nb + tx*4 + j] = acc[i][j];
    float a1v[4], a2v[4];
#pragma unroll
    for (int j = 0; j < 4; j++){ a1v[j] = sa1[tx*4 + j]; a2v[j] = sa2[tx*4 + j]; }
    float fmax_local = -INFINITY;
#pragma unroll
    for (int i = 0; i < 4; i++){
        float p1 = acc[i][0]*a1v[0] + acc[i][1]*a1v[1] + acc[i][2]*a1v[2] + acc[i][3]*a1v[3];
        float p2 = acc[i][0]*a2v[0] + acc[i][1]*a2v[1] + acc[i][2]*a2v[2] + acc[i][3]*a2v[3];
#pragma unroll
        for (int off = 8; off > 0; off >>= 1){
            p1 += __shfl_down_sync(0xffffffffu, p1, off, 16);
            p2 += __shfl_down_sync(0xffffffffu, p2, off, 16);
        }
        if (tx == 0){
            int row = mb + ty*4 + i;
            g_F1[h*NN + row] = p1;
            g_F2[h*NN + row] = p2;
            fmax_local = fmaxf(fmax_local, p2);
        }
    }
    if (tx == 0) smaxs[ty] = fmax_local;
    __syncthreads();
    if (tid == 0){
        float m = smaxs[0];
#pragma unroll
        for (int k = 1; k < 16; k++) m = fmaxf(m, smaxs[k]);
        atomicMax(&g_f2max1u[h], fenc(m));
    }
}

// ---------------- K3: V fp16 (hi only) + ones column, fused bdf1 --------------
__global__ void vbf_kernel(){
    int tid = threadIdx.x;            // grid (64, NH), 256 threads
    int jb = blockIdx.x, h = blockIdx.y;
    if (tid < 64){
        int j = jb*64 + tid;
        float f2 = g_F2[h*NN + j];
        float d  = f2 - fdec(g_f2max1u[h]);
        g_bdf1[h*NN + j] = make_float4(f2, expf(d), expf(0.01f*d), 0.f);
    }
    int j = jb*64 + (tid >> 2);
    int fg = tid & 3;
    const float4* src = reinterpret_cast<const float4*>(g_H1 + (size_t)j*ND + h*HID + fg*16);
    __half* dhi = g_Vb + ((size_t)h*NN + j)*80 + fg*16;
    uint32_t ph[8];
#pragma unroll
    for (int q = 0; q < 4; q++){
        float4 v = src[q];
        ph[q*2]   = pack2f(v.x, v.y);
        ph[q*2+1] = pack2f(v.z, v.w);
    }
    uint4* oh = reinterpret_cast<uint4*>(dhi);
    oh[0] = make_uint4(ph[0],ph[1],ph[2],ph[3]);
    oh[1] = make_uint4(ph[4],ph[5],ph[6],ph[7]);
    if (fg == 3){
        uint4* zh = reinterpret_cast<uint4*>(dhi + 16);
        zh[0] = make_uint4(0x00003C00u, 0u, 0u, 0u);
        zh[1] = make_uint4(0u, 0u, 0u, 0u);
    }
}

// ---------------- phase-A weight producer (shared) -----------------------------
__device__ __forceinline__ void produce_row(
    const uint8_t* adjrow_t, const float4* sbdf,
    float f1, float alpha, float beta,
    int jg, __half* dstA, int row)
{
    uint4 a0 = *reinterpret_cast<const uint4*>(adjrow_t + jg*32);
    uint4 a1 = *reinterpret_cast<const uint4*>(adjrow_t + jg*32 + 16);
    uint32_t aw[8] = {a0.x, a0.y, a0.z, a0.w, a1.x, a1.y, a1.z, a1.w};
    uint32_t oh[16];
#pragma unroll
    for (int p = 0; p < 16; p++){
        int jj = jg*32 + 2*p;
        float4 b0 = sbdf[jj], b1 = sbdf[jj + 1];
        float s0 = f1 + b0.x, s1 = f1 + b1.x;
        float t0 = s0 > 0.f ? b0.y : b0.z;
        float t1 = s1 > 0.f ? b1.y : b1.z;
        float c0 = s0 > 0.f ? alpha : beta;
        float c1 = s1 > 0.f ? alpha : beta;
        uint32_t word = aw[p >> 1];
        uint32_t sh = (p & 1) * 16;
        uint32_t b0b = (word >> sh) & 0xFFu;
        uint32_t b1b = (word >> (sh + 8)) & 0xFFu;
        uint32_t z = ((b0b != 0u && s0 != 0.f) ? 0x0000FFFFu : 0u)
                   | ((b1b != 0u && s1 != 0.f) ? 0xFFFF0000u : 0u);
        oh[p] = pack2f(t0*c0, t1*c1) & z;
    }
    uint4* dh = reinterpret_cast<uint4*>(dstA + row*64 + jg*32);
    dh[0] = make_uint4(oh[0], oh[1], oh[2], oh[3]);
    dh[1] = make_uint4(oh[4], oh[5], oh[6], oh[7]);
    dh[2] = make_uint4(oh[8], oh[9], oh[10], oh[11]);
    dh[3] = make_uint4(oh[12], oh[13], oh[14], oh[15]);
}

// ---------------- K4: attn1 pipelined wmma (hi-only A and B) ------------------
// dyn smem: AH[2][64][64] 16K | BH[2][64][80] 20K | bdf[2][64]f4 2K = 38912
#define A1_AH(b)  ((__half*)(dsm + (b)*8192))
#define A1_BH(b)  ((__half*)(dsm + 16384 + (b)*10240))
#define A1_BDF(b) ((float4*)(dsm + 36864 + (b)*1024))
#define A1_TOT    38912

__global__ void __launch_bounds__(256) attn1_wmma_kernel(){
    extern __shared__ __align__(16) unsigned char dsm[];
    float* sepi = (float*)dsm;

    int tid = threadIdx.x;
    int wid = tid >> 5;
    int row0 = blockIdx.x * 64;
    int h = blockIdx.y;
    const __half* Vh = g_Vb + (size_t)h*NN*80;
    const float4* bdfg = g_bdf1 + h*NN;

    int tp = tid - 128;
    int prow = tp >> 1, pjg = tp & 1;
    float f1 = 0.f, alpha = 0.f, beta = 0.f;
    const uint8_t* adjrow = nullptr;
    if (tid >= 128){
        f1 = g_F1[h*NN + row0 + prow];
        float tt = f1 + fdec(g_f2max1u[h]);
        float M  = tt > 0.f ? tt : 0.01f*tt;
        alpha = expf(tt - M); beta = expf(0.01f*tt - M);
        adjrow = g_adj8 + (size_t)(row0 + prow)*NN;
    }

    wmma::fragment<wmma::accumulator,16,16,16,float> G[5];
#pragma unroll
    for (int nt = 0; nt < 5; nt++) wmma::fill_fragment(G[nt], 0.f);

    if (tid < 64) A1_BDF(0)[tid] = bdfg[tid];
    __syncthreads();
    if (tid >= 128){
        produce_row(adjrow, A1_BDF(0), f1, alpha, beta, pjg, A1_AH(0), prow);
        if (tp < 64) A1_BDF(1)[tp] = bdfg[64 + tp];
    } else {
        int j = tid >> 1, ch = (tid & 1)*40;
        const uint4* sh4 = reinterpret_cast<const uint4*>(Vh + (size_t)j*80 + ch);
        uint4* dh4 = reinterpret_cast<uint4*>(A1_BH(0) + j*80 + ch);
#pragma unroll
        for (int q = 0; q < 5; q++) dh4[q] = sh4[q];
    }
    __syncthreads();

    for (int t = 0; t < 64; t++){
        int p = t & 1;
        if (tid >= 128){
            if (t < 63)
                produce_row(adjrow + (t+1)*64, A1_BDF(p^1), f1, alpha, beta,
                            pjg, A1_AH(p^1), prow);
            if (t < 62 && tp < 64) A1_BDF(p)[tp] = bdfg[(t+2)*64 + tp];
        } else {
            if (t < 63){
                int j = tid >> 1, ch = (tid & 1)*40;
                size_t jb = (size_t)((t+1)*64 + j)*80 + ch;
                const uint4* sh4 = reinterpret_cast<const uint4*>(Vh + jb);
                uint4* dh4 = reinterpret_cast<uint4*>(A1_BH(p^1) + j*80 + ch);
#pragma unroll
                for (int q = 0; q < 5; q++) dh4[q] = sh4[q];
            }
            const __half* Ab = A1_AH(p) + wid*16*64;
            const __half* Bh = A1_BH(p);
#pragma unroll
            for (int ks = 0; ks < 4; ks++){
                wmma::fragment<wmma::matrix_a,16,16,16,__half,wmma::row_major> ah;
                wmma::load_matrix_sync(ah, Ab + ks*16, 64);
#pragma unroll
                for (int nt = 0; nt < 5; nt++){
                    wmma::fragment<wmma::matrix_b,16,16,16,__half,wmma::row_major> bh;
                    wmma::load_matrix_sync(bh, Bh + ks*16*80 + nt*16, 80);
                    wmma::mma_sync(G[nt], ah, bh, G[nt]);
                }
            }
        }
        __syncthreads();
    }
    if (wid < 4){
#pragma unroll
        for (int nt = 0; nt < 5; nt++)
            wmma::store_matrix_sync(sepi + wid*16*80 + nt*16, G[nt], 80, wmma::mem_row_major);
    }
    __syncthreads();
    {
        int r = tid >> 2, cg = (tid & 3)*16;
        float rz = 1.f / sepi[r*80 + 64];
        float* dst = g_H2 + (size_t)(row0 + r)*ND + h*HID + cg;
#pragma unroll
        for (int c = 0; c < 16; c += 4){
            float o[4];
#pragma unroll
            for (int e = 0; e < 4; e++){
                float v = sepi[r*80 + cg + c + e] * rz;
                o[e] = v > 0.f ? v : expm1f(v);
            }
            *reinterpret_cast<float4*>(dst + c) = make_float4(o[0], o[1], o[2], o[3]);
        }
    }
}

// ---------------- K5: G2 = H2 @ W2^T + f-vectors + fused max ------------------
__global__ void gemm2_kernel(const float* __restrict__ W2,
                             const float* __restrict__ a1, const float* __restrict__ a2){
    __shared__ float sW[16][257];
    __shared__ float sa1[16], sa2[16];
    __shared__ float s_u2[16];
    int tid = threadIdx.x;
    for (int u = tid; u < 16*256; u += 256) sW[u >> 8][u & 255] = W2[u];
    if (tid < 16){ sa1[tid] = a1[tid]; sa2[tid] = a2[tid]; }
    __syncthreads();
    int idx = blockIdx.x*256 + tid;
    int i = idx >> 4, c = idx & 15;
    const float4* hr = reinterpret_cast<const float4*>(g_H2 + i*ND);
    float acc = 0.f;
#pragma unroll 4
    for (int k4 = 0; k4 < 64; k4++){
        float4 v = hr[k4];
        acc += v.x*sW[c][k4*4] + v.y*sW[c][k4*4+1] + v.z*sW[c][k4*4+2] + v.w*sW[c][k4*4+3];
    }
    g_G2[idx] = acc;
    float u1 = acc*sa1[c], u2 = acc*sa2[c];
#pragma unroll
    for (int off = 8; off > 0; off >>= 1){
        u1 += __shfl_down_sync(0xffffffffu, u1, off, 16);
        u2 += __shfl_down_sync(0xffffffffu, u2, off, 16);
    }
    if (c == 0){ g_f1b[i] = u1; g_f2b[i] = u2; s_u2[tid >> 4] = u2; }
    __syncthreads();
    if (tid == 0){
        float m = s_u2[0];
#pragma unroll
        for (int k = 1; k < 16; k++) m = fmaxf(m, s_u2[k]);
        atomicMax(g_f2max2u, fenc(m));
    }
}

// ---------------- K6: bdf2 + G2 fp16 (hi only) split --------------------------
__global__ void bdf2g2_kernel(){
    int row = blockIdx.x*256 + threadIdx.x;   // grid 16
    float f2 = g_f2b[row];
    float d  = f2 - fdec(g_f2max2u[0]);
    g_bdf2[row] = make_float4(f2, expf(d), expf(0.01f*d), 0.f);

    const float4* src = reinterpret_cast<const float4*>(g_G2 + row*NC);
    uint32_t ph[16];
#pragma unroll
    for (int q = 0; q < 4; q++){
        float4 v = src[q];
        ph[q*2]   = pack2f(v.x, v.y);
        ph[q*2+1] = pack2f(v.z, v.w);
    }
    ph[8] = 0x00003C00u;
#pragma unroll
    for (int k = 9; k < 16; k++) ph[k] = 0u;
    uint4* dh = reinterpret_cast<uint4*>(g_G2b + (size_t)row*32);
#pragma unroll
    for (int k = 0; k < 4; k++)
        dh[k] = make_uint4(ph[4*k], ph[4*k+1], ph[4*k+2], ph[4*k+3]);
}

// ---------------- K7: attn2 pipelined wmma (hi only) -> logits ----------------
#define A2_AH(b)  ((__half*)(smem2 + (b)*8192))
#define A2_BH(b)  ((__half*)(smem2 + 16384 + (b)*4096))
#define A2_BDF(b) ((float4*)(smem2 + 24576 + (b)*1024))

__global__ void __launch_bounds__(256) attn2_wmma_kernel(float* __restrict__ out){
    __shared__ __align__(16) unsigned char smem2[26624];
    float* sepi = (float*)smem2;

    int tid = threadIdx.x;
    int wid = tid >> 5;
    int row0 = blockIdx.x * 64;

    int tp = tid - 128;
    int prow = tp >> 1, pjg = tp & 1;
    float f1 = 0.f, alpha = 0.f, beta = 0.f;
    const uint8_t* adjrow = nullptr;
    if (tid >= 128){
        f1 = g_f1b[row0 + prow];
        float tt = f1 + fdec(g_f2max2u[0]);
        float M  = tt > 0.f ? tt : 0.01f*tt;
        alpha = expf(tt - M); beta = expf(0.01f*tt - M);
        adjrow = g_adj8 + (size_t)(row0 + prow)*NN;
    }

    wmma::fragment<wmma::accumulator,16,16,16,float> G[2];
    wmma::fill_fragment(G[0], 0.f);
    wmma::fill_fragment(G[1], 0.f);

    if (tid < 64) A2_BDF(0)[tid] = g_bdf2[tid];
    __syncthreads();
    if (tid >= 128){
        produce_row(adjrow, A2_BDF(0), f1, alpha, beta, pjg, A2_AH(0), prow);
        if (tp < 64) A2_BDF(1)[tp] = g_bdf2[64 + tp];
    } else if (tid < 64){
        const uint4* src = reinterpret_cast<const uint4*>(g_G2b + (size_t)tid*32);
        uint4* dst = reinterpret_cast<uint4*>(A2_BH(0) + tid*32);
#pragma unroll
        for (int q = 0; q < 4; q++) dst[q] = src[q];
    }
    __syncthreads();

    for (int t = 0; t < 64; t++){
        int p = t & 1;
        if (tid >= 128){
            if (t < 63)
                produce_row(adjrow + (t+1)*64, A2_BDF(p^1), f1, alpha, beta,
                            pjg, A2_AH(p^1), prow);
            if (t < 62 && tp < 64) A2_BDF(p)[tp] = g_bdf2[(t+2)*64 + tp];
        } else {
            if (t < 63 && tid < 64){
                const uint4* src = reinterpret_cast<const uint4*>(
                    g_G2b + (size_t)((t+1)*64 + tid)*32);
                uint4* dst = reinterpret_cast<uint4*>(A2_BH(p^1) + tid*32);
#pragma unroll
                for (int q = 0; q < 4; q++) dst[q] = src[q];
            }
            const __half* Ab = A2_AH(p) + wid*16*64;
            const __half* Bh = A2_BH(p);
#pragma unroll
            for (int ks = 0; ks < 4; ks++){
                wmma::fragment<wmma::matrix_a,16,16,16,__half,wmma::row_major> ah;
                wmma::load_matrix_sync(ah, Ab + ks*16, 64);
#pragma unroll
                for (int nt = 0; nt < 2; nt++){
                    wmma::fragment<wmma::matrix_b,16,16,16,__half,wmma::row_major> bh;
                    wmma::load_matrix_sync(bh, Bh + ks*16*32 + nt*16, 32);
                    wmma::mma_sync(G[nt], ah, bh, G[nt]);
                }
            }
        }
        __syncthreads();
    }
    if (wid < 4){
        wmma::store_matrix_sync(sepi + wid*16*32,      G[0], 32, wmma::mem_row_major);
        wmma::store_matrix_sync(sepi + wid*16*32 + 16, G[1], 32, wmma::mem_row_major);
    }
    __syncthreads();
    {
        int r = tid >> 2, cg = (tid & 3)*4;
        float rz = 1.f / sepi[r*32 + 16];
        float o[4];
#pragma unroll
        for (int e = 0; e < 4; e++) o[e] = sepi[r*32 + cg + e] * rz;
        *reinterpret_cast<float4*>(out + (size_t)(row0 + r)*NC + cg)
            = make_float4(o[0], o[1], o[2], o[3]);
    }
}

// ---------------- launch ------------------------------------------------------
extern "C" void kernel_launch(void* const* d_in, const int* in_sizes, int n_in,
                              void* d_out, int out_size){
    const float* x    = (const float*)d_in[0];
    const int*   adj  = (const int*)  d_in[1];
    const float* W1   = (const float*)d_in[2];
    const float* a1_1 = (const float*)d_in[3];
    const float* a2_1 = (const float*)d_in[4];
    const float* W2   = (const float*)d_in[5];
    const float* a1_2 = (const float*)d_in[6];
    const float* a2_2 = (const float*)d_in[7];
    float* out = (float*)d_out;

    static int smem_set = 0;
    if (!smem_set){
        cudaFuncSetAttribute(attn1_wmma_kernel,
                             cudaFuncAttributeMaxDynamicSharedMemorySize, A1_TOT);
        smem_set = 1;
    }

    init_kernel<<<1, 32>>>();
    adj8_kernel<<<4096, 256>>>(adj);
    gemm1_kernel<<<dim3(64, NH), 256>>>(x, W1, a1_1, a2_1);
    vbf_kernel<<<dim3(64, NH), 256>>>();
    attn1_wmma_kernel<<<dim3(64, NH), 256, A1_TOT>>>();
    gemm2_kernel<<<256, 256>>>(W2, a1_2, a2_2);
    bdf2g2_kernel<<<16, 256>>>();
    attn2_wmma_kernel<<<64, 256>>>(out);
}

// round 12
// speedup vs baseline: 2.9177x; 1.5963x over previous
#include <cuda_runtime.h>
#include <cuda_fp16.h>
#include <mma.h>
#include <math.h>
#include <stdint.h>

using namespace nvcuda;

#define NN 4096
#define ND 256
#define HID 64
#define NH 4
#define NC 16

// ---------------- scratch (static device globals) ---------------------------
__device__ float  g_H1[NN*ND];
__device__ float  g_F1[NH*NN];
__device__ float  g_F2[NH*NN];
__device__ unsigned g_f2max1u[NH];
__device__ uint8_t g_adj8[(size_t)NN*NN];
__device__ uint4  g_bd1h[NH*2048];           // per j-pair packed half2 {f2,B,D,0}
__device__ __half g_Vb[(size_t)NH*NN*80];    // [head][j][80] hi only (col64 = ones)
__device__ float  g_H2[NN*ND];
__device__ float  g_G2[NN*NC];
__device__ __half g_G2b[NN*32];              // [j][32] hi only (col16 = ones)
__device__ uint4  g_bd2h[2048];
__device__ float  g_f1b[NN];
__device__ float  g_f2b[NN];
__device__ unsigned g_f2max2u[1];

// ---------------- helpers -----------------------------------------------------
__device__ __forceinline__ unsigned fenc(float f){
    unsigned u = __float_as_uint(f);
    return (u & 0x80000000u) ? ~u : (u | 0x80000000u);
}
__device__ __forceinline__ float fdec(unsigned u){
    return (u & 0x80000000u) ? __uint_as_float(u ^ 0x80000000u) : __uint_as_float(~u);
}
__device__ __forceinline__ uint32_t pack2f(float a, float b){
    __half2 h = __floats2half2_rn(a, b);
    return *reinterpret_cast<uint32_t*>(&h);
}

// ---------------- K0: adjacency -> bytes (+ init atomic cells) ----------------
__global__ void adj8_kernel(const int* __restrict__ adj){
    if (blockIdx.x == 0 && threadIdx.x <= NH){
        if (threadIdx.x < NH) g_f2max1u[threadIdx.x] = 0u;
        else g_f2max2u[0] = 0u;
    }
    size_t idx = (size_t)blockIdx.x*256 + threadIdx.x;   // grid 4096
    const int4* s = reinterpret_cast<const int4*>(adj) + idx*4;
    uint32_t w[4];
#pragma unroll
    for (int q = 0; q < 4; q++){
        int4 v = s[q];
        w[q] = (v.x != 0 ? 1u : 0u) | (v.y != 0 ? 1u : 0u) << 8
             | (v.z != 0 ? 1u : 0u) << 16 | (v.w != 0 ? 1u : 0u) << 24;
    }
    reinterpret_cast<uint4*>(g_adj8)[idx] = make_uint4(w[0], w[1], w[2], w[3]);
}

// ---------------- K1: H1 = x @ W1^T, fused f1/f2 + per-head max ---------------
__global__ void gemm1_kernel(const float* __restrict__ X, const float* __restrict__ W,
                             const float* __restrict__ A1, const float* __restrict__ A2){
    __shared__ float sx[64][17];
    __shared__ float sw[64][17];
    __shared__ float sa1[64], sa2[64], smaxs[16];
    int tid = threadIdx.x;
    int tx = tid & 15, ty = tid >> 4;
    int mb = blockIdx.x * 64, h = blockIdx.y, nb = h * 64;
    if (tid < 64) sa1[tid] = A1[nb + tid];
    else if (tid < 128) sa2[tid - 64] = A2[nb + tid - 64];
    float acc[4][4] = {};
    for (int kb = 0; kb < ND; kb += 16){
        __syncthreads();
        for (int u = tid; u < 64*16; u += 256){
            int m = u >> 4, k = u & 15;
            sx[m][k] = X[(mb + m)*ND + kb + k];
        }
        for (int u = tid; u < 64*16; u += 256){
            int n = u >> 4, k = u & 15;
            sw[n][k] = W[(nb + n)*ND + kb + k];
        }
        __syncthreads();
#pragma unroll
        for (int k = 0; k < 16; k++){
            float a[4], b[4];
#pragma unroll
            for (int r = 0; r < 4; r++){ a[r] = sx[ty*4 + r][k]; b[r] = sw[tx*4 + r][k]; }
#pragma unroll
            for (int i = 0; i < 4; i++)
#pragma unroll
                for (int j = 0; j < 4; j++) acc[i][j] += a[i]*b[j];
        }
    }
#pragma unroll
    for (int i = 0; i < 4; i++)
#pragma unroll
        for (int j = 0; j < 4; j++)
            g_H1[(mb + ty*4 + i)*ND + nb + tx*4 + j] = acc[i][j];
    float a1v[4], a2v[4];
#pragma unroll
    for (int j = 0; j < 4; j++){ a1v[j] = sa1[tx*4 + j]; a2v[j] = sa2[tx*4 + j]; }
    float fmax_local = -INFINITY;
#pragma unroll
    for (int i = 0; i < 4; i++){
        float p1 = acc[i][0]*a1v[0] + acc[i][1]*a1v[1] + acc[i][2]*a1v[2] + acc[i][3]*a1v[3];
        float p2 = acc[i][0]*a2v[0] + acc[i][1]*a2v[1] + acc[i][2]*a2v[2] + acc[i][3]*a2v[3];
#pragma unroll
        for (int off = 8; off > 0; off >>= 1){
            p1 += __shfl_down_sync(0xffffffffu, p1, off, 16);
            p2 += __shfl_down_sync(0xffffffffu, p2, off, 16);
        }
        if (tx == 0){
            int row = mb + ty*4 + i;
            g_F1[h*NN + row] = p1;
            g_F2[h*NN + row] = p2;
            fmax_local = fmaxf(fmax_local, p2);
        }
    }
    if (tx == 0) smaxs[ty] = fmax_local;
    __syncthreads();
    if (tid == 0){
        float m = smaxs[0];
#pragma unroll
        for (int k = 1; k < 16; k++) m = fmaxf(m, smaxs[k]);
        atomicMax(&g_f2max1u[h], fenc(m));
    }
}

// ---------------- K2: V fp16 + ones column, packed bdf table ------------------
__global__ void vbf_kernel(){
    __shared__ float sf[64], sB[64], sD[64];
    int tid = threadIdx.x;            // grid (64, NH), 256 threads
    int jb = blockIdx.x, h = blockIdx.y;
    if (tid < 64){
        int j = jb*64 + tid;
        float f2 = g_F2[h*NN + j];
        float d  = f2 - fdec(g_f2max1u[h]);
        sf[tid] = f2; sB[tid] = expf(d); sD[tid] = expf(0.01f*d);
    }
    __syncthreads();
    if (tid < 32){
        uint4 T;
        T.x = pack2f(sf[2*tid], sf[2*tid + 1]);
        T.y = pack2f(sB[2*tid], sB[2*tid + 1]);
        T.z = pack2f(sD[2*tid], sD[2*tid + 1]);
        T.w = 0u;
        g_bd1h[h*2048 + jb*32 + tid] = T;
    }
    int j = jb*64 + (tid >> 2);
    int fg = tid & 3;
    const float4* src = reinterpret_cast<const float4*>(g_H1 + (size_t)j*ND + h*HID + fg*16);
    __half* dhi = g_Vb + ((size_t)h*NN + j)*80 + fg*16;
    uint32_t ph[8];
#pragma unroll
    for (int q = 0; q < 4; q++){
        float4 v = src[q];
        ph[q*2]   = pack2f(v.x, v.y);
        ph[q*2+1] = pack2f(v.z, v.w);
    }
    uint4* oh = reinterpret_cast<uint4*>(dhi);
    oh[0] = make_uint4(ph[0],ph[1],ph[2],ph[3]);
    oh[1] = make_uint4(ph[4],ph[5],ph[6],ph[7]);
    if (fg == 3){
        uint4* zh = reinterpret_cast<uint4*>(dhi + 16);
        zh[0] = make_uint4(0x00003C00u, 0u, 0u, 0u);
        zh[1] = make_uint4(0u, 0u, 0u, 0u);
    }
}

// ---------------- fp16x2 phase-A weight producer ------------------------------
// 32 fp16 weights (one row, jg half) -> dstA row stride 72 halves
__device__ __forceinline__ void produce_row_h2(
    const uint8_t* adjrow_t, const uint4* sT,
    uint32_t f1h2, uint32_t gp2, uint32_t gn2,
    int jg, __half* dstA, int row)
{
    uint4 a0 = *reinterpret_cast<const uint4*>(adjrow_t + jg*32);
    uint4 a1 = *reinterpret_cast<const uint4*>(adjrow_t + jg*32 + 16);
    uint32_t aw[8] = {a0.x, a0.y, a0.z, a0.w, a1.x, a1.y, a1.z, a1.w};
    const __half2 z2 = __float2half2_rn(0.f);
    uint32_t oh[16];
#pragma unroll
    for (int p = 0; p < 16; p++){
        uint4 T = sT[jg*16 + p];
        __half2 s2 = __hadd2(*reinterpret_cast<const __half2*>(&f1h2),
                             *reinterpret_cast<const __half2*>(&T.x));
        uint32_t m = __hgt2_mask(s2, z2);
        __half2 wp = __hmul2(*reinterpret_cast<const __half2*>(&gp2),
                             *reinterpret_cast<const __half2*>(&T.y));
        __half2 wn = __hmul2(*reinterpret_cast<const __half2*>(&gn2),
                             *reinterpret_cast<const __half2*>(&T.z));
        uint32_t wpu = *reinterpret_cast<uint32_t*>(&wp);
        uint32_t wnu = *reinterpret_cast<uint32_t*>(&wn);
        uint32_t sel = (wpu & m) | (wnu & ~m);
        uint32_t word = aw[p >> 1], sh = (p & 1)*16;
        uint32_t b0 = (word >> sh) & 0xFFu;
        uint32_t b1 = (word >> (sh + 8)) & 0xFFu;
        oh[p] = sel & (b0*0xFFFFu + b1*0xFFFF0000u);
    }
    uint4* dh = reinterpret_cast<uint4*>(dstA + row*72 + jg*32);
    dh[0] = make_uint4(oh[0], oh[1], oh[2], oh[3]);
    dh[1] = make_uint4(oh[4], oh[5], oh[6], oh[7]);
    dh[2] = make_uint4(oh[8], oh[9], oh[10], oh[11]);
    dh[3] = make_uint4(oh[12], oh[13], oh[14], oh[15]);
}

// ---------------- K3: attn1 pipelined wmma, padded tiles ----------------------
// dyn smem: AH[2][64][72] 18432 | BH[2][64][88] 22528 | T[2][32]u4 1024 = 41984
#define A1_AH(b)  ((__half*)(dsm + (b)*9216))
#define A1_BH(b)  ((__half*)(dsm + 18432 + (b)*11264))
#define A1_T(b)   ((uint4*)(dsm + 40960 + (b)*512))
#define A1_TOT    41984

__global__ void __launch_bounds__(256) attn1_wmma_kernel(){
    extern __shared__ __align__(16) unsigned char dsm[];
    float* sepi = (float*)dsm;

    int tid = threadIdx.x;
    int wid = tid >> 5;
    int row0 = blockIdx.x * 64;
    int h = blockIdx.y;
    const __half* Vh = g_Vb + (size_t)h*NN*80;
    const uint4* bdg = g_bd1h + h*2048;

    int tp = tid - 128;
    int prow = tp >> 1, pjg = tp & 1;
    uint32_t f1h2 = 0, gp2 = 0, gn2 = 0;
    const uint8_t* adjrow = nullptr;
    if (tid >= 128){
        float f1 = g_F1[h*NN + row0 + prow];
        float tt = f1 + fdec(g_f2max1u[h]);
        float gp = tt >= 0.f ? 1.f : expf(0.99f*tt);
        float gn = tt >= 0.f ? expf(-0.99f*tt) : 1.f;
        f1h2 = pack2f(f1, f1); gp2 = pack2f(gp, gp); gn2 = pack2f(gn, gn);
        adjrow = g_adj8 + (size_t)(row0 + prow)*NN;
    }

    wmma::fragment<wmma::accumulator,16,16,16,float> G[5];
#pragma unroll
    for (int nt = 0; nt < 5; nt++) wmma::fill_fragment(G[nt], 0.f);

    if (tid < 32) A1_T(0)[tid] = bdg[tid];
    __syncthreads();
    if (tid >= 128){
        produce_row_h2(adjrow, A1_T(0), f1h2, gp2, gn2, pjg, A1_AH(0), prow);
        if (tp < 32) A1_T(1)[tp] = bdg[32 + tp];
    } else {
        int j = tid >> 1, ch = (tid & 1)*40;
        const uint4* sh4 = reinterpret_cast<const uint4*>(Vh + (size_t)j*80 + ch);
        uint4* dh4 = reinterpret_cast<uint4*>(A1_BH(0) + j*88 + ch);
#pragma unroll
        for (int q = 0; q < 5; q++) dh4[q] = sh4[q];
    }
    __syncthreads();

    for (int t = 0; t < 64; t++){
        int p = t & 1;
        if (tid >= 128){
            if (t < 63)
                produce_row_h2(adjrow + (t+1)*64, A1_T(p^1), f1h2, gp2, gn2,
                               pjg, A1_AH(p^1), prow);
            if (t < 62 && tp < 32) A1_T(p)[tp] = bdg[(t+2)*32 + tp];
        } else {
            if (t < 63){
                int j = tid >> 1, ch = (tid & 1)*40;
                size_t jb = (size_t)((t+1)*64 + j)*80 + ch;
                const uint4* sh4 = reinterpret_cast<const uint4*>(Vh + jb);
                uint4* dh4 = reinterpret_cast<uint4*>(A1_BH(p^1) + j*88 + ch);
#pragma unroll
                for (int q = 0; q < 5; q++) dh4[q] = sh4[q];
            }
            const __half* Ab = A1_AH(p) + wid*16*72;
            const __half* Bh = A1_BH(p);
#pragma unroll
            for (int ks = 0; ks < 4; ks++){
                wmma::fragment<wmma::matrix_a,16,16,16,__half,wmma::row_major> ah;
                wmma::load_matrix_sync(ah, Ab + ks*16, 72);
#pragma unroll
                for (int nt = 0; nt < 5; nt++){
                    wmma::fragment<wmma::matrix_b,16,16,16,__half,wmma::row_major> bh;
                    wmma::load_matrix_sync(bh, Bh + ks*16*88 + nt*16, 88);
                    wmma::mma_sync(G[nt], ah, bh, G[nt]);
                }
            }
        }
        __syncthreads();
    }
    if (wid < 4){
#pragma unroll
        for (int nt = 0; nt < 5; nt++)
            wmma::store_matrix_sync(sepi + wid*16*80 + nt*16, G[nt], 80, wmma::mem_row_major);
    }
    __syncthreads();
    {
        int r = tid >> 2, cg = (tid & 3)*16;
        float rz = 1.f / sepi[r*80 + 64];
        float* dst = g_H2 + (size_t)(row0 + r)*ND + h*HID + cg;
#pragma unroll
        for (int c = 0; c < 16; c += 4){
            float o[4];
#pragma unroll
            for (int e = 0; e < 4; e++){
                float v = sepi[r*80 + cg + c + e] * rz;
                o[e] = v > 0.f ? v : expm1f(v);
            }
            *reinterpret_cast<float4*>(dst + c) = make_float4(o[0], o[1], o[2], o[3]);
        }
    }
}

// ---------------- K4: G2 = H2 @ W2^T + f-vectors + fused max ------------------
__global__ void gemm2_kernel(const float* __restrict__ W2,
                             const float* __restrict__ a1, const float* __restrict__ a2){
    __shared__ float sW[16][257];
    __shared__ float sa1[16], sa2[16];
    __shared__ float s_u2[16];
    int tid = threadIdx.x;
    for (int u = tid; u < 16*256; u += 256) sW[u >> 8][u & 255] = W2[u];
    if (tid < 16){ sa1[tid] = a1[tid]; sa2[tid] = a2[tid]; }
    __syncthreads();
    int idx = blockIdx.x*256 + tid;
    int i = idx >> 4, c = idx & 15;
    const float4* hr = reinterpret_cast<const float4*>(g_H2 + i*ND);
    float acc = 0.f;
#pragma unroll 4
    for (int k4 = 0; k4 < 64; k4++){
        float4 v = hr[k4];
        acc += v.x*sW[c][k4*4] + v.y*sW[c][k4*4+1] + v.z*sW[c][k4*4+2] + v.w*sW[c][k4*4+3];
    }
    g_G2[idx] = acc;
    float u1 = acc*sa1[c], u2 = acc*sa2[c];
#pragma unroll
    for (int off = 8; off > 0; off >>= 1){
        u1 += __shfl_down_sync(0xffffffffu, u1, off, 16);
        u2 += __shfl_down_sync(0xffffffffu, u2, off, 16);
    }
    if (c == 0){ g_f1b[i] = u1; g_f2b[i] = u2; s_u2[tid >> 4] = u2; }
    __syncthreads();
    if (tid == 0){
        float m = s_u2[0];
#pragma unroll
        for (int k = 1; k < 16; k++) m = fmaxf(m, s_u2[k]);
        atomicMax(g_f2max2u, fenc(m));
    }
}

// ---------------- K5: packed bdf2 table + G2 fp16 split -----------------------
__global__ void bdf2g2_kernel(){
    int row = blockIdx.x*256 + threadIdx.x;   // grid 16
    float f2 = g_f2b[row];
    float d  = f2 - fdec(g_f2max2u[0]);
    float B = expf(d), D = expf(0.01f*d);
    float f2n = __shfl_down_sync(0xffffffffu, f2, 1);
    float Bn  = __shfl_down_sync(0xffffffffu, B, 1);
    float Dn  = __shfl_down_sync(0xffffffffu, D, 1);
    if (!(row & 1)){
        uint4 T;
        T.x = pack2f(f2, f2n); T.y = pack2f(B, Bn); T.z = pack2f(D, Dn); T.w = 0u;
        g_bd2h[row >> 1] = T;
    }
    const float4* src = reinterpret_cast<const float4*>(g_G2 + row*NC);
    uint32_t ph[16];
#pragma unroll
    for (int q = 0; q < 4; q++){
        float4 v = src[q];
        ph[q*2]   = pack2f(v.x, v.y);
        ph[q*2+1] = pack2f(v.z, v.w);
    }
    ph[8] = 0x00003C00u;
#pragma unroll
    for (int k = 9; k < 16; k++) ph[k] = 0u;
    uint4* dh = reinterpret_cast<uint4*>(g_G2b + (size_t)row*32);
#pragma unroll
    for (int k = 0; k < 4; k++)
        dh[k] = make_uint4(ph[4*k], ph[4*k+1], ph[4*k+2], ph[4*k+3]);
}

// ---------------- K6: attn2 pipelined wmma, padded tiles ----------------------
// static smem: AH[2][64][72] 18432 | BH[2][64][40] 10240 | T[2][32] 1024 = 29696
#define A2_AH(b)  ((__half*)(smem2 + (b)*9216))
#define A2_BH(b)  ((__half*)(smem2 + 18432 + (b)*5120))
#define A2_T(b)   ((uint4*)(smem2 + 28672 + (b)*512))

__global__ void __launch_bounds__(256) attn2_wmma_kernel(float* __restrict__ out){
    __shared__ __align__(16) unsigned char smem2[29696];
    float* sepi = (float*)smem2;

    int tid = threadIdx.x;
    int wid = tid >> 5;
    int row0 = blockIdx.x * 64;

    int tp = tid - 128;
    int prow = tp >> 1, pjg = tp & 1;
    uint32_t f1h2 = 0, gp2 = 0, gn2 = 0;
    const uint8_t* adjrow = nullptr;
    if (tid >= 128){
        float f1 = g_f1b[row0 + prow];
        float tt = f1 + fdec(g_f2max2u[0]);
        float gp = tt >= 0.f ? 1.f : expf(0.99f*tt);
        float gn = tt >= 0.f ? expf(-0.99f*tt) : 1.f;
        f1h2 = pack2f(f1, f1); gp2 = pack2f(gp, gp); gn2 = pack2f(gn, gn);
        adjrow = g_adj8 + (size_t)(row0 + prow)*NN;
    }

    wmma::fragment<wmma::accumulator,16,16,16,float> G[2];
    wmma::fill_fragment(G[0], 0.f);
    wmma::fill_fragment(G[1], 0.f);

    if (tid < 32) A2_T(0)[tid] = g_bd2h[tid];
    __syncthreads();
    if (tid >= 128){
        produce_row_h2(adjrow, A2_T(0), f1h2, gp2, gn2, pjg, A2_AH(0), prow);
        if (tp < 32) A2_T(1)[tp] = g_bd2h[32 + tp];
    } else if (tid < 64){
        const uint4* src = reinterpret_cast<const uint4*>(g_G2b + (size_t)tid*32);
        uint4* dst = reinterpret_cast<uint4*>(A2_BH(0) + tid*40);
#pragma unroll
        for (int q = 0; q < 4; q++) dst[q] = src[q];
    }
    __syncthreads();

    for (int t = 0; t < 64; t++){
        int p = t & 1;
        if (tid >= 128){
            if (t < 63)
                produce_row_h2(adjrow + (t+1)*64, A2_T(p^1), f1h2, gp2, gn2,
                               pjg, A2_AH(p^1), prow);
            if (t < 62 && tp < 32) A2_T(p)[tp] = g_bd2h[(t+2)*32 + tp];
        } else {
            if (t < 63 && tid < 64){
                const uint4* src = reinterpret_cast<const uint4*>(
                    g_G2b + (size_t)((t+1)*64 + tid)*32);
                uint4* dst = reinterpret_cast<uint4*>(A2_BH(p^1) + tid*40);
#pragma unroll
                for (int q = 0; q < 4; q++) dst[q] = src[q];
            }
            const __half* Ab = A2_AH(p) + wid*16*72;
            const __half* Bh = A2_BH(p);
#pragma unroll
            for (int ks = 0; ks < 4; ks++){
                wmma::fragment<wmma::matrix_a,16,16,16,__half,wmma::row_major> ah;
                wmma::load_matrix_sync(ah, Ab + ks*16, 72);
#pragma unroll
                for (int nt = 0; nt < 2; nt++){
                    wmma::fragment<wmma::matrix_b,16,16,16,__half,wmma::row_major> bh;
                    wmma::load_matrix_sync(bh, Bh + ks*16*40 + nt*16, 40);
                    wmma::mma_sync(G[nt], ah, bh, G[nt]);
                }
            }
        }
        __syncthreads();
    }
    if (wid < 4){
        wmma::store_matrix_sync(sepi + wid*16*32,      G[0], 32, wmma::mem_row_major);
        wmma::store_matrix_sync(sepi + wid*16*32 + 16, G[1], 32, wmma::mem_row_major);
    }
    __syncthreads();
    {
        int r = tid >> 2, cg = (tid & 3)*4;
        float rz = 1.f / sepi[r*32 + 16];
        float o[4];
#pragma unroll
        for (int e = 0; e < 4; e++) o[e] = sepi[r*32 + cg + e] * rz;
        *reinterpret_cast<float4*>(out + (size_t)(row0 + r)*NC + cg)
            = make_float4(o[0], o[1], o[2], o[3]);
    }
}

// ---------------- launch ------------------------------------------------------
extern "C" void kernel_launch(void* const* d_in, const int* in_sizes, int n_in,
                              void* d_out, int out_size){
    const float* x    = (const float*)d_in[0];
    const int*   adj  = (const int*)  d_in[1];
    const float* W1   = (const float*)d_in[2];
    const float* a1_1 = (const float*)d_in[3];
    const float* a2_1 = (const float*)d_in[4];
    const float* W2   = (const float*)d_in[5];
    const float* a1_2 = (const float*)d_in[6];
    const float* a2_2 = (const float*)d_in[7];
    float* out = (float*)d_out;

    static int smem_set = 0;
    if (!smem_set){
        cudaFuncSetAttribute(attn1_wmma_kernel,
                             cudaFuncAttributeMaxDynamicSharedMemorySize, A1_TOT);
        smem_set = 1;
    }

    adj8_kernel<<<4096, 256>>>(adj);                       // launch 0
    gemm1_kernel<<<dim3(64, NH), 256>>>(x, W1, a1_1, a2_1);// launch 1
    vbf_kernel<<<dim3(64, NH), 256>>>();                   // launch 2
    attn1_wmma_kernel<<<dim3(64, NH), 256, A1_TOT>>>();    // launch 3 (ncu target)
    gemm2_kernel<<<256, 256>>>(W2, a1_2, a2_2);
    bdf2g2_kernel<<<16, 256>>>();
    attn2_wmma_kernel<<<64, 256>>>(out);
}